// round 6
// baseline (speedup 1.0000x reference)
#include <cuda_runtime.h>
#include <cuda_bf16.h>
#include <cstdint>

// Problem constants
constexpr int BB    = 8;      // batch
constexpr int HH    = 32;     // height
constexpr int WWI   = 32;     // width
constexpr int NN    = 1024;   // tokens = H*W
constexpr int CD    = 512;    // dim
constexpr int NHEAD = 16;
constexpr int HD    = 32;     // head dim
constexpr int MTOT  = BB * NN;   // 8192 rows
constexpr int KKG   = 512;       // GEMM K (both GEMMs)

// ---------------------------------------------------------------------------
// Scratch (device globals; no allocation allowed)
// ---------------------------------------------------------------------------
__device__ float g_y[MTOT * CD];                    // attn out (fp32)
__device__ __nv_bfloat16 g_xh[MTOT * CD],  g_xl[MTOT * CD];
__device__ __nv_bfloat16 g_yh[MTOT * CD],  g_yl[MTOT * CD];
__device__ __nv_bfloat16 g_wqh[3 * CD * CD], g_wql[3 * CD * CD];
__device__ __nv_bfloat16 g_wph[CD * CD],     g_wpl[CD * CD];
// Q/K/V in bf16 hi/lo, layout [(b*NHEAD+h)][N][HD]
constexpr int QKV_ELEMS = BB * NHEAD * NN * HD;
__device__ __nv_bfloat16 g_qh[QKV_ELEMS], g_ql[QKV_ELEMS];
__device__ __nv_bfloat16 g_kh[QKV_ELEMS], g_kl[QKV_ELEMS];
__device__ __nv_bfloat16 g_vh[QKV_ELEMS], g_vl[QKV_ELEMS];

// ---------------------------------------------------------------------------
// PTX helpers — sm_103-base ISA only (NO tcgen05: harness PTX targets sm_103)
// ---------------------------------------------------------------------------
__device__ __forceinline__ uint32_t smem_u32(const void* p) {
    uint32_t a;
    asm("{ .reg .u64 t; cvta.to.shared.u64 t, %1; cvt.u32.u64 %0, t; }" : "=r"(a) : "l"(p));
    return a;
}

__device__ __forceinline__ void cp_async16(uint32_t s, const void* g) {
    asm volatile("cp.async.cg.shared.global [%0], [%1], 16;" :: "r"(s), "l"(g));
}

#define CP_COMMIT() asm volatile("cp.async.commit_group;")
#define CP_WAIT1()  asm volatile("cp.async.wait_group 1;")
#define CP_WAIT0()  asm volatile("cp.async.wait_group 0;")

#define LDSM_X4(R, addr)                                                     \
    asm volatile("ldmatrix.sync.aligned.m8n8.x4.shared.b16 {%0,%1,%2,%3}, [%4];" \
        : "=r"((R)[0]), "=r"((R)[1]), "=r"((R)[2]), "=r"((R)[3]) : "r"(addr))

#define LDSM_X4_T(R, addr)                                                   \
    asm volatile("ldmatrix.sync.aligned.m8n8.x4.trans.shared.b16 {%0,%1,%2,%3}, [%4];" \
        : "=r"((R)[0]), "=r"((R)[1]), "=r"((R)[2]), "=r"((R)[3]) : "r"(addr))

#define MMA16816(C, A, B0, B1)                                               \
    asm volatile("mma.sync.aligned.m16n8k16.row.col.f32.bf16.bf16.f32 "      \
        "{%0,%1,%2,%3}, {%4,%5,%6,%7}, {%8,%9}, {%0,%1,%2,%3};"              \
        : "+f"((C)[0]), "+f"((C)[1]), "+f"((C)[2]), "+f"((C)[3])             \
        : "r"((A)[0]), "r"((A)[1]), "r"((A)[2]), "r"((A)[3]),                \
          "r"(B0), "r"(B1))

__device__ __forceinline__ float ex2(float x) {
    float r;
    asm("ex2.approx.f32 %0, %1;" : "=f"(r) : "f"(x));
    return r;
}

// SW64 swizzle: 64B rows, 16B segments; conflict-free for ldmatrix + cp.async
__device__ __forceinline__ uint32_t sw64(int row, int seg) {
    return (uint32_t)(row * 64 + ((seg ^ ((row >> 1) & 3)) << 4));
}

__device__ __forceinline__ uint32_t pack_bf2(__nv_bfloat16 lo, __nv_bfloat16 hi) {
    unsigned short a = __bfloat16_as_ushort(lo);
    unsigned short b = __bfloat16_as_ushort(hi);
    return (uint32_t)a | ((uint32_t)b << 16);
}

__device__ __forceinline__ void split_pack(float a, float b, uint32_t& hp, uint32_t& lp) {
    __nv_bfloat16 ha = __float2bfloat16(a);
    __nv_bfloat16 hb = __float2bfloat16(b);
    __nv_bfloat16 la = __float2bfloat16(a - __bfloat162float(ha));
    __nv_bfloat16 lb = __float2bfloat16(b - __bfloat162float(hb));
    hp = pack_bf2(ha, hb);
    lp = pack_bf2(la, lb);
}

// ---------------------------------------------------------------------------
// fp32 -> (bf16 hi, bf16 lo) split; float4 per thread
// ---------------------------------------------------------------------------
__global__ __launch_bounds__(256) void split_kernel(
    const float* __restrict__ s, __nv_bfloat16* __restrict__ hi,
    __nv_bfloat16* __restrict__ lo, int n4)
{
    int i = blockIdx.x * blockDim.x + threadIdx.x;
    if (i >= n4) return;
    float4 v = ((const float4*)s)[i];
    uint32_t h0, l0, h1, l1;
    split_pack(v.x, v.y, h0, l0);
    split_pack(v.z, v.w, h1, l1);
    ((uint32_t*)hi)[2 * i]     = h0;
    ((uint32_t*)hi)[2 * i + 1] = h1;
    ((uint32_t*)lo)[2 * i]     = l0;
    ((uint32_t*)lo)[2 * i + 1] = l1;
}

// ---------------------------------------------------------------------------
// bf16x3 GEMM via mma.sync:  D[128x128] = (Ah+Al)[128xK] @ (Bh+Bl)[128xK]^T
// MODE 0: write q/k/v bf16 hi/lo arrays.  MODE 1: out = D + bias (fp32).
// 256 threads (8 warps: 4 M x 2 N), warp tile 32x64, K-chunk 32, 3-stage
// cp.async (single barrier per chunk), SW64 64B smem rows. 2 CTAs/SM.
// ---------------------------------------------------------------------------
template <int MODE>
__global__ __launch_bounds__(256, 2) void mma_gemm(
    const __nv_bfloat16* __restrict__ Ah, const __nv_bfloat16* __restrict__ Al,
    const __nv_bfloat16* __restrict__ Bh, const __nv_bfloat16* __restrict__ Bl,
    const float* __restrict__ bias, float* __restrict__ out)
{
    constexpr int TILE  = 128 * 64;           // 8192 B
    constexpr int STAGE = 4 * TILE;           // 32768 B: Ah, Al, Bh, Bl
    constexpr int NCH   = KKG / 32;           // 16 K-chunks

    extern __shared__ char dsm[];
    const uint32_t sbase = smem_u32(dsm);

    const int tid  = threadIdx.x;
    const int lane = tid & 31;
    const int wid  = tid >> 5;
    const int mw   = wid & 3;                 // 0..3 -> M groups of 32
    const int nw   = wid >> 2;                // 0..1 -> N groups of 64
    const int rowBase = blockIdx.y * 128;
    const int colBase = blockIdx.x * 128;

    float acc[2][8][4];
    #pragma unroll
    for (int a = 0; a < 2; a++)
        #pragma unroll
        for (int b = 0; b < 8; b++)
            #pragma unroll
            for (int c = 0; c < 4; c++) acc[a][b][c] = 0.0f;

    const int aRow  = mw * 32 + (lane & 15);
    const int aSeg0 = lane >> 4;
    const int bRow  = nw * 64 + ((lane >> 4) & 1) * 8 + (lane & 7);
    const int bSeg0 = (lane >> 3) & 1;

    auto loadChunk = [&](int ch, int buf) {
        const uint32_t sb = sbase + buf * STAGE;
        #pragma unroll
        for (int rep = 0; rep < 2; rep++) {
            const int id  = tid * 2 + rep;
            const int r   = id >> 2;
            const int seg = id & 3;
            const uint32_t so = sw64(r, seg);
            const size_t  ga = (size_t)(rowBase + r) * KKG + ch * 32 + seg * 8;
            const size_t  gb = (size_t)(colBase + r) * KKG + ch * 32 + seg * 8;
            cp_async16(sb + so,            Ah + ga);
            cp_async16(sb + TILE + so,     Al + ga);
            cp_async16(sb + 2 * TILE + so, Bh + gb);
            cp_async16(sb + 3 * TILE + so, Bl + gb);
        }
    };

    loadChunk(0, 0); CP_COMMIT();
    loadChunk(1, 1); CP_COMMIT();

    for (int ch = 0; ch < NCH; ch++) {
        if (ch + 1 < NCH) CP_WAIT1(); else CP_WAIT0();
        __syncthreads();
        if (ch + 2 < NCH) {
            loadChunk(ch + 2, (ch + 2) % 3);
            CP_COMMIT();
        }

        const uint32_t st = sbase + (ch % 3) * STAGE;
        #pragma unroll
        for (int ks = 0; ks < 2; ks++) {
            uint32_t ah[2][4], al[2][4], bb[4][4];
            #pragma unroll
            for (int mm = 0; mm < 2; mm++) {
                const uint32_t ad = st + sw64(aRow + mm * 16, aSeg0 + 2 * ks);
                LDSM_X4(ah[mm], ad);
                LDSM_X4(al[mm], ad + TILE);
            }
            #pragma unroll
            for (int nb = 0; nb < 4; nb++)
                LDSM_X4(bb[nb], st + 2 * TILE + sw64(bRow + nb * 16, bSeg0 + 2 * ks));

            #pragma unroll
            for (int mm = 0; mm < 2; mm++)
                #pragma unroll
                for (int nf = 0; nf < 8; nf++) {
                    const uint32_t b0 = bb[nf >> 1][(nf & 1) * 2];
                    const uint32_t b1 = bb[nf >> 1][(nf & 1) * 2 + 1];
                    MMA16816(acc[mm][nf], ah[mm], b0, b1);
                    MMA16816(acc[mm][nf], al[mm], b0, b1);
                }

            #pragma unroll
            for (int nb = 0; nb < 4; nb++)
                LDSM_X4(bb[nb], st + 3 * TILE + sw64(bRow + nb * 16, bSeg0 + 2 * ks));

            #pragma unroll
            for (int mm = 0; mm < 2; mm++)
                #pragma unroll
                for (int nf = 0; nf < 8; nf++) {
                    const uint32_t b0 = bb[nf >> 1][(nf & 1) * 2];
                    const uint32_t b1 = bb[nf >> 1][(nf & 1) * 2 + 1];
                    MMA16816(acc[mm][nf], ah[mm], b0, b1);
                }
        }
    }

    // Epilogue. C frag: rows lane/4 (+8), cols (lane%4)*2
    #pragma unroll
    for (int mm = 0; mm < 2; mm++) {
        #pragma unroll
        for (int nf = 0; nf < 8; nf++) {
            const int c = colBase + nw * 64 + nf * 8 + (lane & 3) * 2;
            const int r0 = rowBase + mw * 32 + mm * 16 + (lane >> 2);
            if (MODE == 0) {
                const int three = c >> 9;
                const int head  = (c >> 5) & 15;
                const int d     = c & 31;
                __nv_bfloat16* dh = (three == 0) ? g_qh : (three == 1) ? g_kh : g_vh;
                __nv_bfloat16* dl = (three == 0) ? g_ql : (three == 1) ? g_kl : g_vl;
                #pragma unroll
                for (int half = 0; half < 2; half++) {
                    const int r = r0 + half * 8;
                    const int b = r >> 10, n = r & 1023;
                    const size_t idx = (((size_t)(b * NHEAD + head) * NN) + n) * HD + d;
                    uint32_t hp, lp;
                    split_pack(acc[mm][nf][half * 2], acc[mm][nf][half * 2 + 1], hp, lp);
                    *(uint32_t*)(dh + idx) = hp;
                    *(uint32_t*)(dl + idx) = lp;
                }
            } else {
                const float2 bv = *(const float2*)(bias + c);
                #pragma unroll
                for (int half = 0; half < 2; half++) {
                    const int r = r0 + half * 8;
                    float2 v = make_float2(acc[mm][nf][half * 2] + bv.x,
                                           acc[mm][nf][half * 2 + 1] + bv.y);
                    *(float2*)(out + (size_t)r * CD + c) = v;
                }
            }
        }
    }
}

// ---------------------------------------------------------------------------
// Tensor-core flash attention (bf16 hi/lo splits, fp32 softmax).
// 256 thr / 8 warps; 128 q-rows per block, 16 per warp; 64-key tiles,
// 3-stage cp.async (single barrier per tile), SW64 swizzle. 2 CTAs/SM.
// grid = (NN/128, NHEAD, BB)
// ---------------------------------------------------------------------------
__global__ __launch_bounds__(256, 2) void attn_mma_kernel(float* __restrict__ y)
{
    constexpr int QBYTES = 128 * 64;          // 8192 per matrix
    constexpr int TMAT   = 64 * 64;           // 4096 per kv matrix
    constexpr int STAGE  = 4 * TMAT;          // 16384: kh, kl, vh, vl
    constexpr int NT     = NN / 64;           // 16 tiles
    const float SC  = 0.17677669529663687f;   // 32^-0.5
    const float C2  = 0.17677669529663687f * 1.44269504088896340736f;  // SC*log2e

    extern __shared__ char dsm[];
    const uint32_t sQH = smem_u32(dsm);
    const uint32_t sKV = sQH + 2 * QBYTES;

    const int tid  = threadIdx.x;
    const int lane = tid & 31;
    const int wid  = tid >> 5;
    const int wr   = wid * 16;

    const int b = blockIdx.z;
    const int h = blockIdx.y;
    const int rowBase = blockIdx.x * 128;
    const size_t hb = ((size_t)(b * NHEAD + h)) * NN * HD;

    auto loadKV = [&](int t, int buf) {
        const uint32_t sb = sKV + buf * STAGE;
        const int row = tid >> 2, seg = tid & 3;
        const uint32_t so = sw64(row, seg);
        const size_t g = hb + (size_t)(t * 64 + row) * HD + seg * 8;
        cp_async16(sb + so,            g_kh + g);
        cp_async16(sb + TMAT + so,     g_kl + g);
        cp_async16(sb + 2 * TMAT + so, g_vh + g);
        cp_async16(sb + 3 * TMAT + so, g_vl + g);
    };

    {   // Q load + KV tile 0 -> one group
        #pragma unroll
        for (int rep = 0; rep < 2; rep++) {
            const int id  = tid * 2 + rep;
            const int row = id >> 2, seg = id & 3;
            const uint32_t so = sw64(row, seg);
            const size_t g = hb + (size_t)(rowBase + row) * HD + seg * 8;
            cp_async16(sQH + so,          g_qh + g);
            cp_async16(sQH + QBYTES + so, g_ql + g);
        }
        loadKV(0, 0);
        CP_COMMIT();
        loadKV(1, 1);
        CP_COMMIT();
    }

    float acc[4][4];
    #pragma unroll
    for (int a = 0; a < 4; a++)
        #pragma unroll
        for (int c = 0; c < 4; c++) acc[a][c] = 0.0f;
    float m0 = -1e30f, m1 = -1e30f, l0 = 0.0f, l1 = 0.0f;

    uint32_t qh[2][4], ql[2][4];
    const int qRow = wr + (lane & 15);
    const int qSeg0 = lane >> 4;
    const int kRowL = lane & 7;               // + j*8
    const int kSeg = lane >> 3;
    const int vRowL = ((lane >> 3) & 1) * 8 + (lane & 7);   // + kk*16
    const int vSeg0 = lane >> 4;              // + 2*dp

    for (int t = 0; t < NT; t++) {
        if (t + 1 < NT) CP_WAIT1(); else CP_WAIT0();
        __syncthreads();
        if (t + 2 < NT) {
            loadKV(t + 2, (t + 2) % 3);
            CP_COMMIT();
        }

        if (t == 0) {
            #pragma unroll
            for (int kt = 0; kt < 2; kt++) {
                const uint32_t qa = sQH + sw64(qRow, qSeg0 + 2 * kt);
                LDSM_X4(qh[kt], qa);
                LDSM_X4(ql[kt], qa + QBYTES);
            }
        }

        const uint32_t st = sKV + (t % 3) * STAGE;

        // ---- scores: S = (Qh+Ql)·(Kh+Kl)^T ----
        float s[8][4];
        #pragma unroll
        for (int j = 0; j < 8; j++) {
            uint32_t kf[4], lf[4];
            const uint32_t ka = st + sw64(j * 8 + kRowL, kSeg);
            LDSM_X4(kf, ka);
            LDSM_X4(lf, ka + TMAT);
            s[j][0] = s[j][1] = s[j][2] = s[j][3] = 0.0f;
            MMA16816(s[j], qh[0], kf[0], kf[1]);
            MMA16816(s[j], qh[1], kf[2], kf[3]);
            MMA16816(s[j], qh[0], lf[0], lf[1]);
            MMA16816(s[j], qh[1], lf[2], lf[3]);
            MMA16816(s[j], ql[0], kf[0], kf[1]);
            MMA16816(s[j], ql[1], kf[2], kf[3]);
        }

        // ---- online softmax (exp2 with folded scale) ----
        float mx0 = -1e30f, mx1 = -1e30f;
        #pragma unroll
        for (int j = 0; j < 8; j++) {
            mx0 = fmaxf(mx0, fmaxf(s[j][0], s[j][1]));
            mx1 = fmaxf(mx1, fmaxf(s[j][2], s[j][3]));
        }
        mx0 = fmaxf(mx0, __shfl_xor_sync(0xffffffffu, mx0, 1));
        mx0 = fmaxf(mx0, __shfl_xor_sync(0xffffffffu, mx0, 2));
        mx1 = fmaxf(mx1, __shfl_xor_sync(0xffffffffu, mx1, 1));
        mx1 = fmaxf(mx1, __shfl_xor_sync(0xffffffffu, mx1, 2));
        const float nm0 = fmaxf(m0, mx0), nm1 = fmaxf(m1, mx1);
        const float cf0 = ex2((m0 - nm0) * C2);
        const float cf1 = ex2((m1 - nm1) * C2);
        m0 = nm0; m1 = nm1;
        const float ms0 = nm0 * C2, ms1 = nm1 * C2;
        float ps0 = 0.0f, ps1 = 0.0f;
        #pragma unroll
        for (int j = 0; j < 8; j++) {
            s[j][0] = ex2(fmaf(s[j][0], C2, -ms0));
            s[j][1] = ex2(fmaf(s[j][1], C2, -ms0));
            s[j][2] = ex2(fmaf(s[j][2], C2, -ms1));
            s[j][3] = ex2(fmaf(s[j][3], C2, -ms1));
            ps0 += s[j][0] + s[j][1];
            ps1 += s[j][2] + s[j][3];
        }
        l0 = l0 * cf0 + ps0;
        l1 = l1 * cf1 + ps1;
        #pragma unroll
        for (int a = 0; a < 4; a++) {
            acc[a][0] *= cf0; acc[a][1] *= cf0;
            acc[a][2] *= cf1; acc[a][3] *= cf1;
        }

        // ---- P·V (P register-resident) ----
        #pragma unroll
        for (int kk = 0; kk < 4; kk++) {
            uint32_t ph[4], pl[4];
            split_pack(s[2 * kk][0],     s[2 * kk][1],     ph[0], pl[0]);
            split_pack(s[2 * kk][2],     s[2 * kk][3],     ph[1], pl[1]);
            split_pack(s[2 * kk + 1][0], s[2 * kk + 1][1], ph[2], pl[2]);
            split_pack(s[2 * kk + 1][2], s[2 * kk + 1][3], ph[3], pl[3]);
            #pragma unroll
            for (int dp = 0; dp < 2; dp++) {
                uint32_t vh[4], vl[4];
                const uint32_t va = st + 2 * TMAT + sw64(kk * 16 + vRowL, vSeg0 + 2 * dp);
                LDSM_X4_T(vh, va);
                LDSM_X4_T(vl, va + TMAT);
                MMA16816(acc[2 * dp],     ph, vh[0], vh[1]);
                MMA16816(acc[2 * dp + 1], ph, vh[2], vh[3]);
                MMA16816(acc[2 * dp],     pl, vh[0], vh[1]);
                MMA16816(acc[2 * dp + 1], pl, vh[2], vh[3]);
                MMA16816(acc[2 * dp],     ph, vl[0], vl[1]);
                MMA16816(acc[2 * dp + 1], ph, vl[2], vl[3]);
            }
        }
    }

    l0 += __shfl_xor_sync(0xffffffffu, l0, 1);
    l0 += __shfl_xor_sync(0xffffffffu, l0, 2);
    l1 += __shfl_xor_sync(0xffffffffu, l1, 1);
    l1 += __shfl_xor_sync(0xffffffffu, l1, 2);
    const float inv0 = 1.0f / l0, inv1 = 1.0f / l1;

    const int r0 = rowBase + wr + (lane >> 2);
    const int cB = h * HD + (lane & 3) * 2;
    #pragma unroll
    for (int dn = 0; dn < 4; dn++) {
        *(float2*)(y + (size_t)(b * NN + r0) * CD + cB + dn * 8) =
            make_float2(acc[dn][0] * inv0, acc[dn][1] * inv0);
        *(float2*)(y + (size_t)(b * NN + r0 + 8) * CD + cB + dn * 8) =
            make_float2(acc[dn][2] * inv1, acc[dn][3] * inv1);
    }
}

// ---------------------------------------------------------------------------
// Fused LePE + split: yh/yl = split( y_attn + dwconv5x5(x) + bias )
// grid = (W, H, B), block = 128 threads (4 channels each)
// ---------------------------------------------------------------------------
__global__ __launch_bounds__(128) void lepe_split_kernel(
    const float* __restrict__ x, const float* __restrict__ wl,
    const float* __restrict__ bl, const float* __restrict__ y,
    __nv_bfloat16* __restrict__ yh, __nv_bfloat16* __restrict__ yl)
{
    const int b  = blockIdx.z;
    const int yy = blockIdx.y;
    const int xx = blockIdx.x;
    const int c  = threadIdx.x * 4;

    float4 sum = *(const float4*)&bl[c];
    #pragma unroll
    for (int ky = 0; ky < 5; ky++) {
        const int iy = yy + ky - 2;
        if (iy < 0 || iy >= HH) continue;
        #pragma unroll
        for (int kx = 0; kx < 5; kx++) {
            const int ix = xx + kx - 2;
            if (ix < 0 || ix >= WWI) continue;
            const float4 xv = *(const float4*)&x[(((size_t)(b * HH + iy) * WWI + ix) * CD) + c];
            const int wk = ky * 5 + kx;
            sum.x = fmaf(xv.x, wl[(c + 0) * 25 + wk], sum.x);
            sum.y = fmaf(xv.y, wl[(c + 1) * 25 + wk], sum.y);
            sum.z = fmaf(xv.z, wl[(c + 2) * 25 + wk], sum.z);
            sum.w = fmaf(xv.w, wl[(c + 3) * 25 + wk], sum.w);
        }
    }
    const size_t idx = (((size_t)b * NN + yy * WWI + xx) * CD) + c;
    const float4 av = *(const float4*)&y[idx];
    sum.x += av.x; sum.y += av.y; sum.z += av.z; sum.w += av.w;
    uint32_t h0, l0, h1, l1;
    split_pack(sum.x, sum.y, h0, l0);
    split_pack(sum.z, sum.w, h1, l1);
    uint32_t* H = (uint32_t*)(yh + idx);
    uint32_t* L = (uint32_t*)(yl + idx);
    H[0] = h0; H[1] = h1;
    L[0] = l0; L[1] = l1;
}

// ---------------------------------------------------------------------------
extern "C" void kernel_launch(void* const* d_in, const int* in_sizes, int n_in,
                              void* d_out, int out_size)
{
    const float* x      = (const float*)d_in[0];
    const float* w_qkv  = (const float*)d_in[1];
    const float* w_proj = (const float*)d_in[2];
    const float* b_proj = (const float*)d_in[3];
    const float* w_lepe = (const float*)d_in[4];
    const float* b_lepe = (const float*)d_in[5];
    float* out = (float*)d_out;

    float *yPtr;
    __nv_bfloat16 *xh, *xl, *yh, *yl, *wqh, *wql, *wph, *wpl;
    cudaGetSymbolAddress((void**)&yPtr, g_y);
    cudaGetSymbolAddress((void**)&xh, g_xh);   cudaGetSymbolAddress((void**)&xl, g_xl);
    cudaGetSymbolAddress((void**)&yh, g_yh);   cudaGetSymbolAddress((void**)&yl, g_yl);
    cudaGetSymbolAddress((void**)&wqh, g_wqh); cudaGetSymbolAddress((void**)&wql, g_wql);
    cudaGetSymbolAddress((void**)&wph, g_wph); cudaGetSymbolAddress((void**)&wpl, g_wpl);

    constexpr int SMEM_GEMM = 3 * 4 * 128 * 64;                // 98304 B (3-stage)
    constexpr int SMEM_ATTN = 2 * 128 * 64 + 3 * 4 * 64 * 64;  // 16384 + 49152 = 65536 B
    cudaFuncSetAttribute(mma_gemm<0>, cudaFuncAttributeMaxDynamicSharedMemorySize, SMEM_GEMM);
    cudaFuncSetAttribute(mma_gemm<1>, cudaFuncAttributeMaxDynamicSharedMemorySize, SMEM_GEMM);
    cudaFuncSetAttribute(attn_mma_kernel, cudaFuncAttributeMaxDynamicSharedMemorySize, SMEM_ATTN);

    // 0) split inputs/weights to bf16 hi/lo
    {
        int n4 = MTOT * CD / 4;
        split_kernel<<<(n4 + 255) / 256, 256>>>(x, xh, xl, n4);
        int w4 = 3 * CD * CD / 4;
        split_kernel<<<(w4 + 255) / 256, 256>>>(w_qkv, wqh, wql, w4);
        int p4 = CD * CD / 4;
        split_kernel<<<(p4 + 255) / 256, 256>>>(w_proj, wph, wpl, p4);
    }
    // 1) QKV projection -> g_{q,k,v}{h,l}   (M=8192, N=1536, K=512)
    {
        dim3 grid(3 * CD / 128, MTOT / 128);
        mma_gemm<0><<<grid, 256, SMEM_GEMM>>>(xh, xl, wqh, wql, nullptr, nullptr);
    }
    // 2) Attention -> g_y (fp32)
    {
        dim3 grid(NN / 128, NHEAD, BB);
        attn_mma_kernel<<<grid, 256, SMEM_ATTN>>>(yPtr);
    }
    // 3) Fused LePE + split -> g_yh/g_yl
    {
        dim3 grid(WWI, HH, BB);
        lepe_split_kernel<<<grid, 128>>>(x, w_lepe, b_lepe, yPtr, yh, yl);
    }
    // 4) Output projection -> d_out  (M=8192, N=512, K=512)
    {
        dim3 grid(CD / 128, MTOT / 128);
        mma_gemm<1><<<grid, 256, SMEM_GEMM>>>(yh, yl, wph, wpl, b_proj, out);
    }
}

// round 11
// speedup vs baseline: 1.0378x; 1.0378x over previous
#include <cuda_runtime.h>
#include <cuda_bf16.h>
#include <cstdint>

// Problem constants
constexpr int BB    = 8;      // batch
constexpr int HH    = 32;     // height
constexpr int WWI   = 32;     // width
constexpr int NN    = 1024;   // tokens = H*W
constexpr int CD    = 512;    // dim
constexpr int NHEAD = 16;
constexpr int HD    = 32;     // head dim
constexpr int MTOT  = BB * NN;   // 8192 rows
constexpr int KKG   = 512;       // GEMM K (both GEMMs)

// ---------------------------------------------------------------------------
// Scratch (device globals; no allocation allowed)
// ---------------------------------------------------------------------------
__device__ float g_y[MTOT * CD];                    // attn out (fp32)
__device__ __nv_bfloat16 g_xh[MTOT * CD],  g_xl[MTOT * CD];
__device__ __nv_bfloat16 g_yh[MTOT * CD],  g_yl[MTOT * CD];
__device__ __nv_bfloat16 g_wqh[3 * CD * CD], g_wql[3 * CD * CD];
__device__ __nv_bfloat16 g_wph[CD * CD],     g_wpl[CD * CD];
// Q/K/V in bf16 hi/lo, layout [(b*NHEAD+h)][N][HD]  (V: hi only is consumed)
constexpr int QKV_ELEMS = BB * NHEAD * NN * HD;
__device__ __nv_bfloat16 g_qh[QKV_ELEMS], g_ql[QKV_ELEMS];
__device__ __nv_bfloat16 g_kh[QKV_ELEMS], g_kl[QKV_ELEMS];
__device__ __nv_bfloat16 g_vh[QKV_ELEMS], g_vl[QKV_ELEMS];

// ---------------------------------------------------------------------------
// PTX helpers — sm_103-base ISA only (NO tcgen05: harness PTX targets sm_103)
// ---------------------------------------------------------------------------
__device__ __forceinline__ uint32_t smem_u32(const void* p) {
    uint32_t a;
    asm("{ .reg .u64 t; cvta.to.shared.u64 t, %1; cvt.u32.u64 %0, t; }" : "=r"(a) : "l"(p));
    return a;
}

__device__ __forceinline__ void cp_async16(uint32_t s, const void* g) {
    asm volatile("cp.async.cg.shared.global [%0], [%1], 16;" :: "r"(s), "l"(g));
}

#define CP_COMMIT() asm volatile("cp.async.commit_group;")
#define CP_WAIT1()  asm volatile("cp.async.wait_group 1;")
#define CP_WAIT0()  asm volatile("cp.async.wait_group 0;")

#define LDSM_X4(R, addr)                                                     \
    asm volatile("ldmatrix.sync.aligned.m8n8.x4.shared.b16 {%0,%1,%2,%3}, [%4];" \
        : "=r"((R)[0]), "=r"((R)[1]), "=r"((R)[2]), "=r"((R)[3]) : "r"(addr))

#define LDSM_X4_T(R, addr)                                                   \
    asm volatile("ldmatrix.sync.aligned.m8n8.x4.trans.shared.b16 {%0,%1,%2,%3}, [%4];" \
        : "=r"((R)[0]), "=r"((R)[1]), "=r"((R)[2]), "=r"((R)[3]) : "r"(addr))

#define MMA16816(C, A, B0, B1)                                               \
    asm volatile("mma.sync.aligned.m16n8k16.row.col.f32.bf16.bf16.f32 "      \
        "{%0,%1,%2,%3}, {%4,%5,%6,%7}, {%8,%9}, {%0,%1,%2,%3};"              \
        : "+f"((C)[0]), "+f"((C)[1]), "+f"((C)[2]), "+f"((C)[3])             \
        : "r"((A)[0]), "r"((A)[1]), "r"((A)[2]), "r"((A)[3]),                \
          "r"(B0), "r"(B1))

__device__ __forceinline__ float ex2(float x) {
    float r;
    asm("ex2.approx.f32 %0, %1;" : "=f"(r) : "f"(x));
    return r;
}

// SW64 swizzle: 64B rows, 16B segments; conflict-free for ldmatrix + cp.async
__device__ __forceinline__ uint32_t sw64(int row, int seg) {
    return (uint32_t)(row * 64 + ((seg ^ ((row >> 1) & 3)) << 4));
}

__device__ __forceinline__ uint32_t pack_bf2(__nv_bfloat16 lo, __nv_bfloat16 hi) {
    unsigned short a = __bfloat16_as_ushort(lo);
    unsigned short b = __bfloat16_as_ushort(hi);
    return (uint32_t)a | ((uint32_t)b << 16);
}

__device__ __forceinline__ void split_pack(float a, float b, uint32_t& hp, uint32_t& lp) {
    __nv_bfloat16 ha = __float2bfloat16(a);
    __nv_bfloat16 hb = __float2bfloat16(b);
    __nv_bfloat16 la = __float2bfloat16(a - __bfloat162float(ha));
    __nv_bfloat16 lb = __float2bfloat16(b - __bfloat162float(hb));
    hp = pack_bf2(ha, hb);
    lp = pack_bf2(la, lb);
}

// ---------------------------------------------------------------------------
// fp32 -> (bf16 hi, bf16 lo) split; float4 per thread
// ---------------------------------------------------------------------------
__global__ __launch_bounds__(256) void split_kernel(
    const float* __restrict__ s, __nv_bfloat16* __restrict__ hi,
    __nv_bfloat16* __restrict__ lo, int n4)
{
    int i = blockIdx.x * blockDim.x + threadIdx.x;
    if (i >= n4) return;
    float4 v = ((const float4*)s)[i];
    uint32_t h0, l0, h1, l1;
    split_pack(v.x, v.y, h0, l0);
    split_pack(v.z, v.w, h1, l1);
    ((uint32_t*)hi)[2 * i]     = h0;
    ((uint32_t*)hi)[2 * i + 1] = h1;
    ((uint32_t*)lo)[2 * i]     = l0;
    ((uint32_t*)lo)[2 * i + 1] = l1;
}

// ---------------------------------------------------------------------------
// bf16x3 GEMM via mma.sync (R5 structure — measured best):
// D[128x128] = (Ah+Al)[128xK] @ (Bh+Bl)[128xK]^T
// MODE 0: write q/k/v bf16 hi/lo arrays.  MODE 1: out = D + bias (fp32).
// 256 threads (8 warps: 4 M x 2 N), warp tile 32x64, K-chunk 32, 2-stage,
// SW64-swizzled 64B smem rows. 2 CTAs/SM.
// ---------------------------------------------------------------------------
template <int MODE>
__global__ __launch_bounds__(256, 2) void mma_gemm(
    const __nv_bfloat16* __restrict__ Ah, const __nv_bfloat16* __restrict__ Al,
    const __nv_bfloat16* __restrict__ Bh, const __nv_bfloat16* __restrict__ Bl,
    const float* __restrict__ bias, float* __restrict__ out)
{
    constexpr int TILE  = 128 * 64;           // 8192 B
    constexpr int STAGE = 4 * TILE;           // 32768 B: Ah, Al, Bh, Bl
    constexpr int NCH   = KKG / 32;           // 16 K-chunks

    extern __shared__ char dsm[];
    const uint32_t sbase = smem_u32(dsm);

    const int tid  = threadIdx.x;
    const int lane = tid & 31;
    const int wid  = tid >> 5;
    const int mw   = wid & 3;                 // 0..3 -> M groups of 32
    const int nw   = wid >> 2;                // 0..1 -> N groups of 64
    const int rowBase = blockIdx.y * 128;
    const int colBase = blockIdx.x * 128;

    float acc[2][8][4];
    #pragma unroll
    for (int a = 0; a < 2; a++)
        #pragma unroll
        for (int b = 0; b < 8; b++)
            #pragma unroll
            for (int c = 0; c < 4; c++) acc[a][b][c] = 0.0f;

    const int aRow  = mw * 32 + (lane & 15);
    const int aSeg0 = lane >> 4;
    const int bRow  = nw * 64 + ((lane >> 4) & 1) * 8 + (lane & 7);
    const int bSeg0 = (lane >> 3) & 1;

    auto loadChunk = [&](int ch, int buf) {
        const uint32_t sb = sbase + buf * STAGE;
        #pragma unroll
        for (int rep = 0; rep < 2; rep++) {
            const int id  = tid * 2 + rep;
            const int r   = id >> 2;
            const int seg = id & 3;
            const uint32_t so = sw64(r, seg);
            const size_t  ga = (size_t)(rowBase + r) * KKG + ch * 32 + seg * 8;
            const size_t  gb = (size_t)(colBase + r) * KKG + ch * 32 + seg * 8;
            cp_async16(sb + so,            Ah + ga);
            cp_async16(sb + TILE + so,     Al + ga);
            cp_async16(sb + 2 * TILE + so, Bh + gb);
            cp_async16(sb + 3 * TILE + so, Bl + gb);
        }
    };

    loadChunk(0, 0);
    CP_COMMIT();

    for (int ch = 0; ch < NCH; ch++) {
        if (ch + 1 < NCH) {
            loadChunk(ch + 1, (ch + 1) & 1);
            CP_COMMIT();
            CP_WAIT1();
        } else {
            CP_WAIT0();
        }
        __syncthreads();

        const uint32_t st = sbase + (ch & 1) * STAGE;
        #pragma unroll
        for (int ks = 0; ks < 2; ks++) {
            uint32_t ah[2][4], al[2][4], bb[4][4];
            #pragma unroll
            for (int mm = 0; mm < 2; mm++) {
                const uint32_t ad = st + sw64(aRow + mm * 16, aSeg0 + 2 * ks);
                LDSM_X4(ah[mm], ad);
                LDSM_X4(al[mm], ad + TILE);
            }
            #pragma unroll
            for (int nb = 0; nb < 4; nb++)
                LDSM_X4(bb[nb], st + 2 * TILE + sw64(bRow + nb * 16, bSeg0 + 2 * ks));

            #pragma unroll
            for (int mm = 0; mm < 2; mm++)
                #pragma unroll
                for (int nf = 0; nf < 8; nf++) {
                    const uint32_t b0 = bb[nf >> 1][(nf & 1) * 2];
                    const uint32_t b1 = bb[nf >> 1][(nf & 1) * 2 + 1];
                    MMA16816(acc[mm][nf], ah[mm], b0, b1);
                    MMA16816(acc[mm][nf], al[mm], b0, b1);
                }

            #pragma unroll
            for (int nb = 0; nb < 4; nb++)
                LDSM_X4(bb[nb], st + 3 * TILE + sw64(bRow + nb * 16, bSeg0 + 2 * ks));

            #pragma unroll
            for (int mm = 0; mm < 2; mm++)
                #pragma unroll
                for (int nf = 0; nf < 8; nf++) {
                    const uint32_t b0 = bb[nf >> 1][(nf & 1) * 2];
                    const uint32_t b1 = bb[nf >> 1][(nf & 1) * 2 + 1];
                    MMA16816(acc[mm][nf], ah[mm], b0, b1);
                }
        }
        __syncthreads();
    }

    // Epilogue. C frag: rows lane/4 (+8), cols (lane%4)*2
    #pragma unroll
    for (int mm = 0; mm < 2; mm++) {
        #pragma unroll
        for (int nf = 0; nf < 8; nf++) {
            const int c = colBase + nw * 64 + nf * 8 + (lane & 3) * 2;
            const int r0 = rowBase + mw * 32 + mm * 16 + (lane >> 2);
            if (MODE == 0) {
                const int three = c >> 9;
                const int head  = (c >> 5) & 15;
                const int d     = c & 31;
                __nv_bfloat16* dh = (three == 0) ? g_qh : (three == 1) ? g_kh : g_vh;
                __nv_bfloat16* dl = (three == 0) ? g_ql : (three == 1) ? g_kl : g_vl;
                #pragma unroll
                for (int half = 0; half < 2; half++) {
                    const int r = r0 + half * 8;
                    const int b = r >> 10, n = r & 1023;
                    const size_t idx = (((size_t)(b * NHEAD + head) * NN) + n) * HD + d;
                    uint32_t hp, lp;
                    split_pack(acc[mm][nf][half * 2], acc[mm][nf][half * 2 + 1], hp, lp);
                    *(uint32_t*)(dh + idx) = hp;
                    *(uint32_t*)(dl + idx) = lp;
                }
            } else {
                const float2 bv = *(const float2*)(bias + c);
                #pragma unroll
                for (int half = 0; half < 2; half++) {
                    const int r = r0 + half * 8;
                    float2 v = make_float2(acc[mm][nf][half * 2] + bv.x,
                                           acc[mm][nf][half * 2 + 1] + bv.y);
                    *(float2*)(out + (size_t)r * CD + c) = v;
                }
            }
        }
    }
}

// ---------------------------------------------------------------------------
// Tensor-core flash attention.
// QK^T: 3-split (qh·kh + qh·kl + ql·kh).  P·V: 2-split (ph+pl)·vh — V hi only.
// 256 thr / 8 warps; 128 q-rows per block, 16 per warp; 64-key tiles,
// 2-stage cp.async, SW64 swizzle. 2 CTAs/SM. grid = (NN/128, NHEAD, BB)
// ---------------------------------------------------------------------------
__global__ __launch_bounds__(256, 2) void attn_mma_kernel(float* __restrict__ y)
{
    constexpr int QBYTES = 128 * 64;          // 8192 per matrix
    constexpr int TMAT   = 64 * 64;           // 4096 per kv matrix
    constexpr int STAGE  = 3 * TMAT;          // 12288: kh, kl, vh
    constexpr int NT     = NN / 64;           // 16 tiles
    const float C2  = 0.17677669529663687f * 1.44269504088896340736f;  // SC*log2e

    extern __shared__ char dsm[];
    const uint32_t sQH = smem_u32(dsm);
    const uint32_t sKV = sQH + 2 * QBYTES;

    const int tid  = threadIdx.x;
    const int lane = tid & 31;
    const int wid  = tid >> 5;
    const int wr   = wid * 16;

    const int b = blockIdx.z;
    const int h = blockIdx.y;
    const int rowBase = blockIdx.x * 128;
    const size_t hb = ((size_t)(b * NHEAD + h)) * NN * HD;

    auto loadKV = [&](int t, int buf) {
        const uint32_t sb = sKV + buf * STAGE;
        const int row = tid >> 2, seg = tid & 3;
        const uint32_t so = sw64(row, seg);
        const size_t g = hb + (size_t)(t * 64 + row) * HD + seg * 8;
        cp_async16(sb + so,            g_kh + g);
        cp_async16(sb + TMAT + so,     g_kl + g);
        cp_async16(sb + 2 * TMAT + so, g_vh + g);
    };

    {   // Q load + KV tile 0 -> one group
        #pragma unroll
        for (int rep = 0; rep < 2; rep++) {
            const int id  = tid * 2 + rep;
            const int row = id >> 2, seg = id & 3;
            const uint32_t so = sw64(row, seg);
            const size_t g = hb + (size_t)(rowBase + row) * HD + seg * 8;
            cp_async16(sQH + so,          g_qh + g);
            cp_async16(sQH + QBYTES + so, g_ql + g);
        }
        loadKV(0, 0);
        CP_COMMIT();
    }

    float acc[4][4];
    #pragma unroll
    for (int a = 0; a < 4; a++)
        #pragma unroll
        for (int c = 0; c < 4; c++) acc[a][c] = 0.0f;
    float m0 = -1e30f, m1 = -1e30f, l0 = 0.0f, l1 = 0.0f;

    uint32_t qh[2][4], ql[2][4];
    const int qRow = wr + (lane & 15);
    const int qSeg0 = lane >> 4;
    const int kRowL = lane & 7;               // + j*8
    const int kSeg = lane >> 3;
    const int vRowL = ((lane >> 3) & 1) * 8 + (lane & 7);   // + kk*16
    const int vSeg0 = lane >> 4;              // + 2*dp

    for (int t = 0; t < NT; t++) {
        if (t + 1 < NT) {
            loadKV(t + 1, (t + 1) & 1);
            CP_COMMIT();
            CP_WAIT1();
        } else {
            CP_WAIT0();
        }
        __syncthreads();

        if (t == 0) {
            #pragma unroll
            for (int kt = 0; kt < 2; kt++) {
                const uint32_t qa = sQH + sw64(qRow, qSeg0 + 2 * kt);
                LDSM_X4(qh[kt], qa);
                LDSM_X4(ql[kt], qa + QBYTES);
            }
        }

        const uint32_t st = sKV + (t & 1) * STAGE;

        // ---- scores: S = (Qh+Ql)·(Kh+Kl)^T  (3-split, full precision) ----
        float s[8][4];
        #pragma unroll
        for (int j = 0; j < 8; j++) {
            uint32_t kf[4], lf[4];
            const uint32_t ka = st + sw64(j * 8 + kRowL, kSeg);
            LDSM_X4(kf, ka);
            LDSM_X4(lf, ka + TMAT);
            s[j][0] = s[j][1] = s[j][2] = s[j][3] = 0.0f;
            MMA16816(s[j], qh[0], kf[0], kf[1]);
            MMA16816(s[j], qh[1], kf[2], kf[3]);
            MMA16816(s[j], qh[0], lf[0], lf[1]);
            MMA16816(s[j], qh[1], lf[2], lf[3]);
            MMA16816(s[j], ql[0], kf[0], kf[1]);
            MMA16816(s[j], ql[1], kf[2], kf[3]);
        }

        // ---- online softmax (exp2 with folded scale) ----
        float mx0 = -1e30f, mx1 = -1e30f;
        #pragma unroll
        for (int j = 0; j < 8; j++) {
            mx0 = fmaxf(mx0, fmaxf(s[j][0], s[j][1]));
            mx1 = fmaxf(mx1, fmaxf(s[j][2], s[j][3]));
        }
        mx0 = fmaxf(mx0, __shfl_xor_sync(0xffffffffu, mx0, 1));
        mx0 = fmaxf(mx0, __shfl_xor_sync(0xffffffffu, mx0, 2));
        mx1 = fmaxf(mx1, __shfl_xor_sync(0xffffffffu, mx1, 1));
        mx1 = fmaxf(mx1, __shfl_xor_sync(0xffffffffu, mx1, 2));
        const float nm0 = fmaxf(m0, mx0), nm1 = fmaxf(m1, mx1);
        const float cf0 = ex2((m0 - nm0) * C2);
        const float cf1 = ex2((m1 - nm1) * C2);
        m0 = nm0; m1 = nm1;
        const float ms0 = nm0 * C2, ms1 = nm1 * C2;
        float ps0 = 0.0f, ps1 = 0.0f;
        #pragma unroll
        for (int j = 0; j < 8; j++) {
            s[j][0] = ex2(fmaf(s[j][0], C2, -ms0));
            s[j][1] = ex2(fmaf(s[j][1], C2, -ms0));
            s[j][2] = ex2(fmaf(s[j][2], C2, -ms1));
            s[j][3] = ex2(fmaf(s[j][3], C2, -ms1));
            ps0 += s[j][0] + s[j][1];
            ps1 += s[j][2] + s[j][3];
        }
        l0 = l0 * cf0 + ps0;
        l1 = l1 * cf1 + ps1;
        #pragma unroll
        for (int a = 0; a < 4; a++) {
            acc[a][0] *= cf0; acc[a][1] *= cf0;
            acc[a][2] *= cf1; acc[a][3] *= cf1;
        }

        // ---- P·V: (Ph+Pl)·Vh  (P 2-split, V hi only) ----
        #pragma unroll
        for (int kk = 0; kk < 4; kk++) {
            uint32_t ph[4], pl[4];
            split_pack(s[2 * kk][0],     s[2 * kk][1],     ph[0], pl[0]);
            split_pack(s[2 * kk][2],     s[2 * kk][3],     ph[1], pl[1]);
            split_pack(s[2 * kk + 1][0], s[2 * kk + 1][1], ph[2], pl[2]);
            split_pack(s[2 * kk + 1][2], s[2 * kk + 1][3], ph[3], pl[3]);
            #pragma unroll
            for (int dp = 0; dp < 2; dp++) {
                uint32_t vh[4];
                const uint32_t va = st + 2 * TMAT + sw64(kk * 16 + vRowL, vSeg0 + 2 * dp);
                LDSM_X4_T(vh, va);
                MMA16816(acc[2 * dp],     ph, vh[0], vh[1]);
                MMA16816(acc[2 * dp + 1], ph, vh[2], vh[3]);
                MMA16816(acc[2 * dp],     pl, vh[0], vh[1]);
                MMA16816(acc[2 * dp + 1], pl, vh[2], vh[3]);
            }
        }
        __syncthreads();
    }

    l0 += __shfl_xor_sync(0xffffffffu, l0, 1);
    l0 += __shfl_xor_sync(0xffffffffu, l0, 2);
    l1 += __shfl_xor_sync(0xffffffffu, l1, 1);
    l1 += __shfl_xor_sync(0xffffffffu, l1, 2);
    const float inv0 = 1.0f / l0, inv1 = 1.0f / l1;

    const int r0 = rowBase + wr + (lane >> 2);
    const int cB = h * HD + (lane & 3) * 2;
    #pragma unroll
    for (int dn = 0; dn < 4; dn++) {
        *(float2*)(y + (size_t)(b * NN + r0) * CD + cB + dn * 8) =
            make_float2(acc[dn][0] * inv0, acc[dn][1] * inv0);
        *(float2*)(y + (size_t)(b * NN + r0 + 8) * CD + cB + dn * 8) =
            make_float2(acc[dn][2] * inv1, acc[dn][3] * inv1);
    }
}

// ---------------------------------------------------------------------------
// Fused LePE + split: yh/yl = split( y_attn + dwconv5x5(x) + bias )
// grid = (W, H, B), block = 128 threads (4 channels each)
// ---------------------------------------------------------------------------
__global__ __launch_bounds__(128) void lepe_split_kernel(
    const float* __restrict__ x, const float* __restrict__ wl,
    const float* __restrict__ bl, const float* __restrict__ y,
    __nv_bfloat16* __restrict__ yh, __nv_bfloat16* __restrict__ yl)
{
    const int b  = blockIdx.z;
    const int yy = blockIdx.y;
    const int xx = blockIdx.x;
    const int c  = threadIdx.x * 4;

    float4 sum = *(const float4*)&bl[c];
    #pragma unroll
    for (int ky = 0; ky < 5; ky++) {
        const int iy = yy + ky - 2;
        if (iy < 0 || iy >= HH) continue;
        #pragma unroll
        for (int kx = 0; kx < 5; kx++) {
            const int ix = xx + kx - 2;
            if (ix < 0 || ix >= WWI) continue;
            const float4 xv = *(const float4*)&x[(((size_t)(b * HH + iy) * WWI + ix) * CD) + c];
            const int wk = ky * 5 + kx;
            sum.x = fmaf(xv.x, wl[(c + 0) * 25 + wk], sum.x);
            sum.y = fmaf(xv.y, wl[(c + 1) * 25 + wk], sum.y);
            sum.z = fmaf(xv.z, wl[(c + 2) * 25 + wk], sum.z);
            sum.w = fmaf(xv.w, wl[(c + 3) * 25 + wk], sum.w);
        }
    }
    const size_t idx = (((size_t)b * NN + yy * WWI + xx) * CD) + c;
    const float4 av = *(const float4*)&y[idx];
    sum.x += av.x; sum.y += av.y; sum.z += av.z; sum.w += av.w;
    uint32_t h0, l0, h1, l1;
    split_pack(sum.x, sum.y, h0, l0);
    split_pack(sum.z, sum.w, h1, l1);
    uint32_t* H = (uint32_t*)(yh + idx);
    uint32_t* L = (uint32_t*)(yl + idx);
    H[0] = h0; H[1] = h1;
    L[0] = l0; L[1] = l1;
}

// ---------------------------------------------------------------------------
extern "C" void kernel_launch(void* const* d_in, const int* in_sizes, int n_in,
                              void* d_out, int out_size)
{
    const float* x      = (const float*)d_in[0];
    const float* w_qkv  = (const float*)d_in[1];
    const float* w_proj = (const float*)d_in[2];
    const float* b_proj = (const float*)d_in[3];
    const float* w_lepe = (const float*)d_in[4];
    const float* b_lepe = (const float*)d_in[5];
    float* out = (float*)d_out;

    float *yPtr;
    __nv_bfloat16 *xh, *xl, *yh, *yl, *wqh, *wql, *wph, *wpl;
    cudaGetSymbolAddress((void**)&yPtr, g_y);
    cudaGetSymbolAddress((void**)&xh, g_xh);   cudaGetSymbolAddress((void**)&xl, g_xl);
    cudaGetSymbolAddress((void**)&yh, g_yh);   cudaGetSymbolAddress((void**)&yl, g_yl);
    cudaGetSymbolAddress((void**)&wqh, g_wqh); cudaGetSymbolAddress((void**)&wql, g_wql);
    cudaGetSymbolAddress((void**)&wph, g_wph); cudaGetSymbolAddress((void**)&wpl, g_wpl);

    constexpr int SMEM_GEMM = 2 * 4 * 128 * 64;                // 65536 B (2-stage)
    constexpr int SMEM_ATTN = 2 * 128 * 64 + 2 * 3 * 64 * 64;  // 16384 + 24576 = 40960 B
    cudaFuncSetAttribute(mma_gemm<0>, cudaFuncAttributeMaxDynamicSharedMemorySize, SMEM_GEMM);
    cudaFuncSetAttribute(mma_gemm<1>, cudaFuncAttributeMaxDynamicSharedMemorySize, SMEM_GEMM);
    cudaFuncSetAttribute(attn_mma_kernel, cudaFuncAttributeMaxDynamicSharedMemorySize, SMEM_ATTN);

    // 0) split inputs/weights to bf16 hi/lo
    {
        int n4 = MTOT * CD / 4;
        split_kernel<<<(n4 + 255) / 256, 256>>>(x, xh, xl, n4);
        int w4 = 3 * CD * CD / 4;
        split_kernel<<<(w4 + 255) / 256, 256>>>(w_qkv, wqh, wql, w4);
        int p4 = CD * CD / 4;
        split_kernel<<<(p4 + 255) / 256, 256>>>(w_proj, wph, wpl, p4);
    }
    // 1) QKV projection -> g_{q,k,v}{h,l}   (M=8192, N=1536, K=512)
    {
        dim3 grid(3 * CD / 128, MTOT / 128);
        mma_gemm<0><<<grid, 256, SMEM_GEMM>>>(xh, xl, wqh, wql, nullptr, nullptr);
    }
    // 2) Attention -> g_y (fp32)
    {
        dim3 grid(NN / 128, NHEAD, BB);
        attn_mma_kernel<<<grid, 256, SMEM_ATTN>>>(yPtr);
    }
    // 3) Fused LePE + split -> g_yh/g_yl
    {
        dim3 grid(WWI, HH, BB);
        lepe_split_kernel<<<grid, 128>>>(x, w_lepe, b_lepe, yPtr, yh, yl);
    }
    // 4) Output projection -> d_out  (M=8192, N=512, K=512)
    {
        dim3 grid(CD / 128, MTOT / 128);
        mma_gemm<1><<<grid, 256, SMEM_GEMM>>>(yh, yl, wph, wpl, b_proj, out);
    }
}

// round 14
// speedup vs baseline: 1.3346x; 1.2859x over previous
#include <cuda_runtime.h>
#include <cuda_fp16.h>
#include <cstdint>

// Problem constants
constexpr int BB    = 8;      // batch
constexpr int HH    = 32;     // height
constexpr int WWI   = 32;     // width
constexpr int NN    = 1024;   // tokens = H*W
constexpr int CD    = 512;    // dim
constexpr int NHEAD = 16;
constexpr int HD    = 32;     // head dim
constexpr int MTOT  = BB * NN;   // 8192 rows
constexpr int KKG   = 512;       // GEMM K (both GEMMs)

// ---------------------------------------------------------------------------
// Scratch (device globals; no allocation allowed) — fp16 scheme
// ---------------------------------------------------------------------------
__device__ float g_y[MTOT * CD];                    // attn out (fp32)
__device__ __half g_xh[MTOT * CD],  g_xl[MTOT * CD];
__device__ __half g_yh[MTOT * CD],  g_yl[MTOT * CD];
__device__ __half g_wqh[3 * CD * CD];               // qkv weight hi only
__device__ __half g_wph[CD * CD], g_wpl[CD * CD];   // proj weight hi/lo
// Q hi/lo, K hi, V hi, layout [(b*NHEAD+h)][N][HD]
constexpr int QKV_ELEMS = BB * NHEAD * NN * HD;
__device__ __half g_qh[QKV_ELEMS], g_ql[QKV_ELEMS];
__device__ __half g_kh[QKV_ELEMS], g_vh[QKV_ELEMS];

// ---------------------------------------------------------------------------
// PTX helpers — sm_103-base ISA only (NO tcgen05: harness PTX targets sm_103)
// ---------------------------------------------------------------------------
__device__ __forceinline__ uint32_t smem_u32(const void* p) {
    uint32_t a;
    asm("{ .reg .u64 t; cvta.to.shared.u64 t, %1; cvt.u32.u64 %0, t; }" : "=r"(a) : "l"(p));
    return a;
}

__device__ __forceinline__ void cp_async16(uint32_t s, const void* g) {
    asm volatile("cp.async.cg.shared.global [%0], [%1], 16;" :: "r"(s), "l"(g));
}

#define CP_COMMIT() asm volatile("cp.async.commit_group;")
#define CP_WAIT1()  asm volatile("cp.async.wait_group 1;")
#define CP_WAIT0()  asm volatile("cp.async.wait_group 0;")

#define LDSM_X4(R, addr)                                                     \
    asm volatile("ldmatrix.sync.aligned.m8n8.x4.shared.b16 {%0,%1,%2,%3}, [%4];" \
        : "=r"((R)[0]), "=r"((R)[1]), "=r"((R)[2]), "=r"((R)[3]) : "r"(addr))

#define LDSM_X4_T(R, addr)                                                   \
    asm volatile("ldmatrix.sync.aligned.m8n8.x4.trans.shared.b16 {%0,%1,%2,%3}, [%4];" \
        : "=r"((R)[0]), "=r"((R)[1]), "=r"((R)[2]), "=r"((R)[3]) : "r"(addr))

// fp16 in / fp32 accumulate
#define MMA16816(C, A, B0, B1)                                               \
    asm volatile("mma.sync.aligned.m16n8k16.row.col.f32.f16.f16.f32 "        \
        "{%0,%1,%2,%3}, {%4,%5,%6,%7}, {%8,%9}, {%0,%1,%2,%3};"              \
        : "+f"((C)[0]), "+f"((C)[1]), "+f"((C)[2]), "+f"((C)[3])             \
        : "r"((A)[0]), "r"((A)[1]), "r"((A)[2]), "r"((A)[3]),                \
          "r"(B0), "r"(B1))

__device__ __forceinline__ float ex2(float x) {
    float r;
    asm("ex2.approx.f32 %0, %1;" : "=f"(r) : "f"(x));
    return r;
}

// SW64 swizzle: 64B rows, 16B segments; conflict-free for ldmatrix + cp.async
__device__ __forceinline__ uint32_t sw64(int row, int seg) {
    return (uint32_t)(row * 64 + ((seg ^ ((row >> 1) & 3)) << 4));
}

__device__ __forceinline__ uint32_t pack_h2(float a, float b) {
    __half2 h = __floats2half2_rn(a, b);
    uint32_t r;
    memcpy(&r, &h, 4);
    return r;
}

// split two fp32 into packed fp16 hi and fp16 lo-residual regs
__device__ __forceinline__ void split_pack_h(float a, float b, uint32_t& hp, uint32_t& lp) {
    __half2 h = __floats2half2_rn(a, b);
    float2 hf = __half22float2(h);
    __half2 l = __floats2half2_rn(a - hf.x, b - hf.y);
    memcpy(&hp, &h, 4);
    memcpy(&lp, &l, 4);
}

// ---------------------------------------------------------------------------
// fp32 -> (fp16 hi, fp16 lo) split; float4 per thread
// ---------------------------------------------------------------------------
__global__ __launch_bounds__(256) void split_kernel(
    const float* __restrict__ s, __half* __restrict__ hi,
    __half* __restrict__ lo, int n4)
{
    int i = blockIdx.x * blockDim.x + threadIdx.x;
    if (i >= n4) return;
    float4 v = ((const float4*)s)[i];
    uint32_t h0, l0, h1, l1;
    split_pack_h(v.x, v.y, h0, l0);
    split_pack_h(v.z, v.w, h1, l1);
    ((uint32_t*)hi)[2 * i]     = h0;
    ((uint32_t*)hi)[2 * i + 1] = h1;
    ((uint32_t*)lo)[2 * i]     = l0;
    ((uint32_t*)lo)[2 * i + 1] = l1;
}

// fp32 -> fp16 hi only
__global__ __launch_bounds__(256) void tohalf_kernel(
    const float* __restrict__ s, __half* __restrict__ hi, int n4)
{
    int i = blockIdx.x * blockDim.x + threadIdx.x;
    if (i >= n4) return;
    float4 v = ((const float4*)s)[i];
    ((uint32_t*)hi)[2 * i]     = pack_h2(v.x, v.y);
    ((uint32_t*)hi)[2 * i + 1] = pack_h2(v.z, v.w);
}

// ---------------------------------------------------------------------------
// fp16 split GEMM via mma.sync:  D[128x128] = A[128xK] @ B[128xK]^T
// MODE 0 (QKV): 2-term (Ah+Al)·Bh; epilogue writes qh/ql, kh, vh.
// MODE 1 (proj): 3-term (Ah+Al)·Bh + Ah·Bl; out = D + bias (fp32).
// 256 threads (8 warps: 4 M x 2 N), warp tile 32x64, K-chunk 32, 2-stage,
// SW64-swizzled 64B smem rows. 2 CTAs/SM.
// ---------------------------------------------------------------------------
template <int MODE>
__global__ __launch_bounds__(256, 2) void mma_gemm(
    const __half* __restrict__ Ah, const __half* __restrict__ Al,
    const __half* __restrict__ Bh, const __half* __restrict__ Bl,
    const float* __restrict__ bias, float* __restrict__ out)
{
    constexpr int TILE   = 128 * 64;          // 8192 B
    constexpr int NTILES = (MODE == 0) ? 3 : 4;
    constexpr int STAGE  = NTILES * TILE;
    constexpr int NCH    = KKG / 32;          // 16 K-chunks

    extern __shared__ char dsm[];
    const uint32_t sbase = smem_u32(dsm);

    const int tid  = threadIdx.x;
    const int lane = tid & 31;
    const int wid  = tid >> 5;
    const int mw   = wid & 3;                 // 0..3 -> M groups of 32
    const int nw   = wid >> 2;                // 0..1 -> N groups of 64
    const int rowBase = blockIdx.y * 128;
    const int colBase = blockIdx.x * 128;

    float acc[2][8][4];
    #pragma unroll
    for (int a = 0; a < 2; a++)
        #pragma unroll
        for (int b = 0; b < 8; b++)
            #pragma unroll
            for (int c = 0; c < 4; c++) acc[a][b][c] = 0.0f;

    const int aRow  = mw * 32 + (lane & 15);
    const int aSeg0 = lane >> 4;
    const int bRow  = nw * 64 + ((lane >> 4) & 1) * 8 + (lane & 7);
    const int bSeg0 = (lane >> 3) & 1;

    auto loadChunk = [&](int ch, int buf) {
        const uint32_t sb = sbase + buf * STAGE;
        #pragma unroll
        for (int rep = 0; rep < 2; rep++) {
            const int id  = tid * 2 + rep;
            const int r   = id >> 2;
            const int seg = id & 3;
            const uint32_t so = sw64(r, seg);
            const size_t  ga = (size_t)(rowBase + r) * KKG + ch * 32 + seg * 8;
            const size_t  gb = (size_t)(colBase + r) * KKG + ch * 32 + seg * 8;
            cp_async16(sb + so,            Ah + ga);
            cp_async16(sb + TILE + so,     Al + ga);
            cp_async16(sb + 2 * TILE + so, Bh + gb);
            if (MODE == 1)
                cp_async16(sb + 3 * TILE + so, Bl + gb);
        }
    };

    loadChunk(0, 0);
    CP_COMMIT();

    for (int ch = 0; ch < NCH; ch++) {
        if (ch + 1 < NCH) {
            loadChunk(ch + 1, (ch + 1) & 1);
            CP_COMMIT();
            CP_WAIT1();
        } else {
            CP_WAIT0();
        }
        __syncthreads();

        const uint32_t st = sbase + (ch & 1) * STAGE;
        #pragma unroll
        for (int ks = 0; ks < 2; ks++) {
            uint32_t ah[2][4], al[2][4], bb[4][4];
            #pragma unroll
            for (int mm = 0; mm < 2; mm++) {
                const uint32_t ad = st + sw64(aRow + mm * 16, aSeg0 + 2 * ks);
                LDSM_X4(ah[mm], ad);
                LDSM_X4(al[mm], ad + TILE);
            }
            #pragma unroll
            for (int nb = 0; nb < 4; nb++)
                LDSM_X4(bb[nb], st + 2 * TILE + sw64(bRow + nb * 16, bSeg0 + 2 * ks));

            #pragma unroll
            for (int mm = 0; mm < 2; mm++)
                #pragma unroll
                for (int nf = 0; nf < 8; nf++) {
                    const uint32_t b0 = bb[nf >> 1][(nf & 1) * 2];
                    const uint32_t b1 = bb[nf >> 1][(nf & 1) * 2 + 1];
                    MMA16816(acc[mm][nf], ah[mm], b0, b1);
                    MMA16816(acc[mm][nf], al[mm], b0, b1);
                }

            if (MODE == 1) {
                #pragma unroll
                for (int nb = 0; nb < 4; nb++)
                    LDSM_X4(bb[nb], st + 3 * TILE + sw64(bRow + nb * 16, bSeg0 + 2 * ks));

                #pragma unroll
                for (int mm = 0; mm < 2; mm++)
                    #pragma unroll
                    for (int nf = 0; nf < 8; nf++) {
                        const uint32_t b0 = bb[nf >> 1][(nf & 1) * 2];
                        const uint32_t b1 = bb[nf >> 1][(nf & 1) * 2 + 1];
                        MMA16816(acc[mm][nf], ah[mm], b0, b1);
                    }
            }
        }
        __syncthreads();
    }

    // Epilogue. C frag: rows lane/4 (+8), cols (lane%4)*2
    #pragma unroll
    for (int mm = 0; mm < 2; mm++) {
        #pragma unroll
        for (int nf = 0; nf < 8; nf++) {
            const int c = colBase + nw * 64 + nf * 8 + (lane & 3) * 2;
            const int r0 = rowBase + mw * 32 + mm * 16 + (lane >> 2);
            if (MODE == 0) {
                const int three = c >> 9;
                const int head  = (c >> 5) & 15;
                const int d     = c & 31;
                #pragma unroll
                for (int half = 0; half < 2; half++) {
                    const int r = r0 + half * 8;
                    const int b = r >> 10, n = r & 1023;
                    const size_t idx = (((size_t)(b * NHEAD + head) * NN) + n) * HD + d;
                    if (three == 0) {
                        uint32_t hp, lp;
                        split_pack_h(acc[mm][nf][half * 2], acc[mm][nf][half * 2 + 1], hp, lp);
                        *(uint32_t*)(g_qh + idx) = hp;
                        *(uint32_t*)(g_ql + idx) = lp;
                    } else {
                        __half* dst = (three == 1) ? g_kh : g_vh;
                        *(uint32_t*)(dst + idx) =
                            pack_h2(acc[mm][nf][half * 2], acc[mm][nf][half * 2 + 1]);
                    }
                }
            } else {
                const float2 bv = *(const float2*)(bias + c);
                #pragma unroll
                for (int half = 0; half < 2; half++) {
                    const int r = r0 + half * 8;
                    float2 v = make_float2(acc[mm][nf][half * 2] + bv.x,
                                           acc[mm][nf][half * 2 + 1] + bv.y);
                    *(float2*)(out + (size_t)r * CD + c) = v;
                }
            }
        }
    }
}

// ---------------------------------------------------------------------------
// Tensor-core flash attention (fp16).
// QK^T: (Qh+Ql)·Kh (2-term).  P·V: Ph·Vh (single term).
// 256 thr / 8 warps; 128 q-rows per block, 16 per warp; 64-key tiles,
// 2-stage cp.async, SW64 swizzle. 2 CTAs/SM. grid = (NN/128, NHEAD, BB)
// ---------------------------------------------------------------------------
__global__ __launch_bounds__(256, 2) void attn_mma_kernel(float* __restrict__ y)
{
    constexpr int QBYTES = 128 * 64;          // 8192 per matrix
    constexpr int TMAT   = 64 * 64;           // 4096 per kv matrix
    constexpr int STAGE  = 2 * TMAT;          // 8192: kh, vh
    constexpr int NT     = NN / 64;           // 16 tiles
    const float C2  = 0.17677669529663687f * 1.44269504088896340736f;  // SC*log2e

    extern __shared__ char dsm[];
    const uint32_t sQH = smem_u32(dsm);
    const uint32_t sKV = sQH + 2 * QBYTES;

    const int tid  = threadIdx.x;
    const int lane = tid & 31;
    const int wid  = tid >> 5;
    const int wr   = wid * 16;

    const int b = blockIdx.z;
    const int h = blockIdx.y;
    const int rowBase = blockIdx.x * 128;
    const size_t hb = ((size_t)(b * NHEAD + h)) * NN * HD;

    auto loadKV = [&](int t, int buf) {
        const uint32_t sb = sKV + buf * STAGE;
        const int row = tid >> 2, seg = tid & 3;
        const uint32_t so = sw64(row, seg);
        const size_t g = hb + (size_t)(t * 64 + row) * HD + seg * 8;
        cp_async16(sb + so,        g_kh + g);
        cp_async16(sb + TMAT + so, g_vh + g);
    };

    {   // Q load + KV tile 0 -> one group
        #pragma unroll
        for (int rep = 0; rep < 2; rep++) {
            const int id  = tid * 2 + rep;
            const int row = id >> 2, seg = id & 3;
            const uint32_t so = sw64(row, seg);
            const size_t g = hb + (size_t)(rowBase + row) * HD + seg * 8;
            cp_async16(sQH + so,          g_qh + g);
            cp_async16(sQH + QBYTES + so, g_ql + g);
        }
        loadKV(0, 0);
        CP_COMMIT();
    }

    float acc[4][4];
    #pragma unroll
    for (int a = 0; a < 4; a++)
        #pragma unroll
        for (int c = 0; c < 4; c++) acc[a][c] = 0.0f;
    float m0 = -1e30f, m1 = -1e30f, l0 = 0.0f, l1 = 0.0f;

    uint32_t qh[2][4], ql[2][4];
    const int qRow = wr + (lane & 15);
    const int qSeg0 = lane >> 4;
    const int kRowL = lane & 7;               // + j*8
    const int kSeg = lane >> 3;
    const int vRowL = ((lane >> 3) & 1) * 8 + (lane & 7);   // + kk*16
    const int vSeg0 = lane >> 4;              // + 2*dp

    for (int t = 0; t < NT; t++) {
        if (t + 1 < NT) {
            loadKV(t + 1, (t + 1) & 1);
            CP_COMMIT();
            CP_WAIT1();
        } else {
            CP_WAIT0();
        }
        __syncthreads();

        if (t == 0) {
            #pragma unroll
            for (int kt = 0; kt < 2; kt++) {
                const uint32_t qa = sQH + sw64(qRow, qSeg0 + 2 * kt);
                LDSM_X4(qh[kt], qa);
                LDSM_X4(ql[kt], qa + QBYTES);
            }
        }

        const uint32_t st = sKV + (t & 1) * STAGE;

        // ---- scores: S = (Qh+Ql)·Kh^T ----
        float s[8][4];
        #pragma unroll
        for (int j = 0; j < 8; j++) {
            uint32_t kf[4];
            LDSM_X4(kf, st + sw64(j * 8 + kRowL, kSeg));
            s[j][0] = s[j][1] = s[j][2] = s[j][3] = 0.0f;
            MMA16816(s[j], qh[0], kf[0], kf[1]);
            MMA16816(s[j], qh[1], kf[2], kf[3]);
            MMA16816(s[j], ql[0], kf[0], kf[1]);
            MMA16816(s[j], ql[1], kf[2], kf[3]);
        }

        // ---- online softmax (exp2 with folded scale) ----
        float mx0 = -1e30f, mx1 = -1e30f;
        #pragma unroll
        for (int j = 0; j < 8; j++) {
            mx0 = fmaxf(mx0, fmaxf(s[j][0], s[j][1]));
            mx1 = fmaxf(mx1, fmaxf(s[j][2], s[j][3]));
        }
        mx0 = fmaxf(mx0, __shfl_xor_sync(0xffffffffu, mx0, 1));
        mx0 = fmaxf(mx0, __shfl_xor_sync(0xffffffffu, mx0, 2));
        mx1 = fmaxf(mx1, __shfl_xor_sync(0xffffffffu, mx1, 1));
        mx1 = fmaxf(mx1, __shfl_xor_sync(0xffffffffu, mx1, 2));
        const float nm0 = fmaxf(m0, mx0), nm1 = fmaxf(m1, mx1);
        const float cf0 = ex2((m0 - nm0) * C2);
        const float cf1 = ex2((m1 - nm1) * C2);
        m0 = nm0; m1 = nm1;
        const float ms0 = nm0 * C2, ms1 = nm1 * C2;
        float ps0 = 0.0f, ps1 = 0.0f;
        #pragma unroll
        for (int j = 0; j < 8; j++) {
            s[j][0] = ex2(fmaf(s[j][0], C2, -ms0));
            s[j][1] = ex2(fmaf(s[j][1], C2, -ms0));
            s[j][2] = ex2(fmaf(s[j][2], C2, -ms1));
            s[j][3] = ex2(fmaf(s[j][3], C2, -ms1));
            ps0 += s[j][0] + s[j][1];
            ps1 += s[j][2] + s[j][3];
        }
        l0 = l0 * cf0 + ps0;
        l1 = l1 * cf1 + ps1;
        #pragma unroll
        for (int a = 0; a < 4; a++) {
            acc[a][0] *= cf0; acc[a][1] *= cf0;
            acc[a][2] *= cf1; acc[a][3] *= cf1;
        }

        // ---- P·V: Ph·Vh  (single fp16 term) ----
        #pragma unroll
        for (int kk = 0; kk < 4; kk++) {
            uint32_t ph[4];
            ph[0] = pack_h2(s[2 * kk][0],     s[2 * kk][1]);
            ph[1] = pack_h2(s[2 * kk][2],     s[2 * kk][3]);
            ph[2] = pack_h2(s[2 * kk + 1][0], s[2 * kk + 1][1]);
            ph[3] = pack_h2(s[2 * kk + 1][2], s[2 * kk + 1][3]);
            #pragma unroll
            for (int dp = 0; dp < 2; dp++) {
                uint32_t vh[4];
                LDSM_X4_T(vh, st + TMAT + sw64(kk * 16 + vRowL, vSeg0 + 2 * dp));
                MMA16816(acc[2 * dp],     ph, vh[0], vh[1]);
                MMA16816(acc[2 * dp + 1], ph, vh[2], vh[3]);
            }
        }
        __syncthreads();
    }

    l0 += __shfl_xor_sync(0xffffffffu, l0, 1);
    l0 += __shfl_xor_sync(0xffffffffu, l0, 2);
    l1 += __shfl_xor_sync(0xffffffffu, l1, 1);
    l1 += __shfl_xor_sync(0xffffffffu, l1, 2);
    const float inv0 = 1.0f / l0, inv1 = 1.0f / l1;

    const int r0 = rowBase + wr + (lane >> 2);
    const int cB = h * HD + (lane & 3) * 2;
    #pragma unroll
    for (int dn = 0; dn < 4; dn++) {
        *(float2*)(y + (size_t)(b * NN + r0) * CD + cB + dn * 8) =
            make_float2(acc[dn][0] * inv0, acc[dn][1] * inv0);
        *(float2*)(y + (size_t)(b * NN + r0 + 8) * CD + cB + dn * 8) =
            make_float2(acc[dn][2] * inv1, acc[dn][3] * inv1);
    }
}

// ---------------------------------------------------------------------------
// Fused LePE + split: yh/yl = split( y_attn + dwconv5x5(x) + bias ), fp16
// grid = (W, H, B), block = 128 threads (4 channels each)
// ---------------------------------------------------------------------------
__global__ __launch_bounds__(128) void lepe_split_kernel(
    const float* __restrict__ x, const float* __restrict__ wl,
    const float* __restrict__ bl, const float* __restrict__ y,
    __half* __restrict__ yh, __half* __restrict__ yl)
{
    const int b  = blockIdx.z;
    const int yy = blockIdx.y;
    const int xx = blockIdx.x;
    const int c  = threadIdx.x * 4;

    float4 sum = *(const float4*)&bl[c];
    #pragma unroll
    for (int ky = 0; ky < 5; ky++) {
        const int iy = yy + ky - 2;
        if (iy < 0 || iy >= HH) continue;
        #pragma unroll
        for (int kx = 0; kx < 5; kx++) {
            const int ix = xx + kx - 2;
            if (ix < 0 || ix >= WWI) continue;
            const float4 xv = *(const float4*)&x[(((size_t)(b * HH + iy) * WWI + ix) * CD) + c];
            const int wk = ky * 5 + kx;
            sum.x = fmaf(xv.x, wl[(c + 0) * 25 + wk], sum.x);
            sum.y = fmaf(xv.y, wl[(c + 1) * 25 + wk], sum.y);
            sum.z = fmaf(xv.z, wl[(c + 2) * 25 + wk], sum.z);
            sum.w = fmaf(xv.w, wl[(c + 3) * 25 + wk], sum.w);
        }
    }
    const size_t idx = (((size_t)b * NN + yy * WWI + xx) * CD) + c;
    const float4 av = *(const float4*)&y[idx];
    sum.x += av.x; sum.y += av.y; sum.z += av.z; sum.w += av.w;
    uint32_t h0, l0, h1, l1;
    split_pack_h(sum.x, sum.y, h0, l0);
    split_pack_h(sum.z, sum.w, h1, l1);
    uint32_t* H = (uint32_t*)(yh + idx);
    uint32_t* L = (uint32_t*)(yl + idx);
    H[0] = h0; H[1] = h1;
    L[0] = l0; L[1] = l1;
}

// ---------------------------------------------------------------------------
extern "C" void kernel_launch(void* const* d_in, const int* in_sizes, int n_in,
                              void* d_out, int out_size)
{
    const float* x      = (const float*)d_in[0];
    const float* w_qkv  = (const float*)d_in[1];
    const float* w_proj = (const float*)d_in[2];
    const float* b_proj = (const float*)d_in[3];
    const float* w_lepe = (const float*)d_in[4];
    const float* b_lepe = (const float*)d_in[5];
    float* out = (float*)d_out;

    float *yPtr;
    __half *xh, *xl, *yh, *yl, *wqh, *wph, *wpl;
    cudaGetSymbolAddress((void**)&yPtr, g_y);
    cudaGetSymbolAddress((void**)&xh, g_xh);   cudaGetSymbolAddress((void**)&xl, g_xl);
    cudaGetSymbolAddress((void**)&yh, g_yh);   cudaGetSymbolAddress((void**)&yl, g_yl);
    cudaGetSymbolAddress((void**)&wqh, g_wqh);
    cudaGetSymbolAddress((void**)&wph, g_wph); cudaGetSymbolAddress((void**)&wpl, g_wpl);

    constexpr int SMEM_GEMM0 = 2 * 3 * 128 * 64;               // 49152 B (3 tiles)
    constexpr int SMEM_GEMM1 = 2 * 4 * 128 * 64;               // 65536 B (4 tiles)
    constexpr int SMEM_ATTN  = 2 * 128 * 64 + 2 * 2 * 64 * 64; // 16384 + 16384 = 32768 B
    cudaFuncSetAttribute(mma_gemm<0>, cudaFuncAttributeMaxDynamicSharedMemorySize, SMEM_GEMM0);
    cudaFuncSetAttribute(mma_gemm<1>, cudaFuncAttributeMaxDynamicSharedMemorySize, SMEM_GEMM1);
    cudaFuncSetAttribute(attn_mma_kernel, cudaFuncAttributeMaxDynamicSharedMemorySize, SMEM_ATTN);

    // 0) convert inputs/weights to fp16
    {
        int n4 = MTOT * CD / 4;
        split_kernel<<<(n4 + 255) / 256, 256>>>(x, xh, xl, n4);
        int w4 = 3 * CD * CD / 4;
        tohalf_kernel<<<(w4 + 255) / 256, 256>>>(w_qkv, wqh, w4);
        int p4 = CD * CD / 4;
        split_kernel<<<(p4 + 255) / 256, 256>>>(w_proj, wph, wpl, p4);
    }
    // 1) QKV projection -> g_qh/g_ql, g_kh, g_vh   (M=8192, N=1536, K=512)
    {
        dim3 grid(3 * CD / 128, MTOT / 128);
        mma_gemm<0><<<grid, 256, SMEM_GEMM0>>>(xh, xl, wqh, nullptr, nullptr, nullptr);
    }
    // 2) Attention -> g_y (fp32)
    {
        dim3 grid(NN / 128, NHEAD, BB);
        attn_mma_kernel<<<grid, 256, SMEM_ATTN>>>(yPtr);
    }
    // 3) Fused LePE + split -> g_yh/g_yl
    {
        dim3 grid(WWI, HH, BB);
        lepe_split_kernel<<<grid, 128>>>(x, w_lepe, b_lepe, yPtr, yh, yl);
    }
    // 4) Output projection -> d_out  (M=8192, N=512, K=512)
    {
        dim3 grid(CD / 128, MTOT / 128);
        mma_gemm<1><<<grid, 256, SMEM_GEMM1>>>(yh, yl, wph, wpl, b_proj, out);
    }
}

// round 15
// speedup vs baseline: 1.5343x; 1.1497x over previous
#include <cuda_runtime.h>
#include <cuda_fp16.h>
#include <cstdint>

// Problem constants
constexpr int BB    = 8;      // batch
constexpr int HH    = 32;     // height
constexpr int WWI   = 32;     // width
constexpr int NN    = 1024;   // tokens = H*W
constexpr int CD    = 512;    // dim
constexpr int NHEAD = 16;
constexpr int HD    = 32;     // head dim
constexpr int MTOT  = BB * NN;   // 8192 rows
constexpr int KKG   = 512;       // GEMM K (both GEMMs)

// ---------------------------------------------------------------------------
// Scratch (device globals; no allocation allowed) — fp16 scheme
// ---------------------------------------------------------------------------
__device__ float g_y[MTOT * CD];                    // attn out (fp32)
__device__ __half g_xh[MTOT * CD];                  // x fp16 (hi only)
__device__ __half g_yh[MTOT * CD],  g_yl[MTOT * CD];
__device__ __half g_wqh[3 * CD * CD];               // qkv weight hi only
__device__ __half g_wph[CD * CD], g_wpl[CD * CD];   // proj weight hi/lo
// Q/K/V fp16, layout [(b*NHEAD+h)][N][HD]
constexpr int QKV_ELEMS = BB * NHEAD * NN * HD;
__device__ __half g_qh[QKV_ELEMS], g_kh[QKV_ELEMS], g_vh[QKV_ELEMS];

// ---------------------------------------------------------------------------
// PTX helpers — sm_103-base ISA only (NO tcgen05: harness PTX targets sm_103)
// ---------------------------------------------------------------------------
__device__ __forceinline__ uint32_t smem_u32(const void* p) {
    uint32_t a;
    asm("{ .reg .u64 t; cvta.to.shared.u64 t, %1; cvt.u32.u64 %0, t; }" : "=r"(a) : "l"(p));
    return a;
}

__device__ __forceinline__ void cp_async16(uint32_t s, const void* g) {
    asm volatile("cp.async.cg.shared.global [%0], [%1], 16;" :: "r"(s), "l"(g));
}

#define CP_COMMIT() asm volatile("cp.async.commit_group;")
#define CP_WAIT1()  asm volatile("cp.async.wait_group 1;")
#define CP_WAIT0()  asm volatile("cp.async.wait_group 0;")

#define LDSM_X4(R, addr)                                                     \
    asm volatile("ldmatrix.sync.aligned.m8n8.x4.shared.b16 {%0,%1,%2,%3}, [%4];" \
        : "=r"((R)[0]), "=r"((R)[1]), "=r"((R)[2]), "=r"((R)[3]) : "r"(addr))

#define LDSM_X4_T(R, addr)                                                   \
    asm volatile("ldmatrix.sync.aligned.m8n8.x4.trans.shared.b16 {%0,%1,%2,%3}, [%4];" \
        : "=r"((R)[0]), "=r"((R)[1]), "=r"((R)[2]), "=r"((R)[3]) : "r"(addr))

// fp16 in / fp32 accumulate
#define MMA16816(C, A, B0, B1)                                               \
    asm volatile("mma.sync.aligned.m16n8k16.row.col.f32.f16.f16.f32 "        \
        "{%0,%1,%2,%3}, {%4,%5,%6,%7}, {%8,%9}, {%0,%1,%2,%3};"              \
        : "+f"((C)[0]), "+f"((C)[1]), "+f"((C)[2]), "+f"((C)[3])             \
        : "r"((A)[0]), "r"((A)[1]), "r"((A)[2]), "r"((A)[3]),                \
          "r"(B0), "r"(B1))

__device__ __forceinline__ float ex2(float x) {
    float r;
    asm("ex2.approx.f32 %0, %1;" : "=f"(r) : "f"(x));
    return r;
}

// SW64 swizzle: 64B rows, 16B segments; conflict-free for ldmatrix + cp.async
__device__ __forceinline__ uint32_t sw64(int row, int seg) {
    return (uint32_t)(row * 64 + ((seg ^ ((row >> 1) & 3)) << 4));
}

__device__ __forceinline__ uint32_t pack_h2(float a, float b) {
    __half2 h = __floats2half2_rn(a, b);
    uint32_t r;
    memcpy(&r, &h, 4);
    return r;
}

// split two fp32 into packed fp16 hi and fp16 lo-residual regs
__device__ __forceinline__ void split_pack_h(float a, float b, uint32_t& hp, uint32_t& lp) {
    __half2 h = __floats2half2_rn(a, b);
    float2 hf = __half22float2(h);
    __half2 l = __floats2half2_rn(a - hf.x, b - hf.y);
    memcpy(&hp, &h, 4);
    memcpy(&lp, &l, 4);
}

// ---------------------------------------------------------------------------
// fp32 -> (fp16 hi, fp16 lo) split; float4 per thread
// ---------------------------------------------------------------------------
__global__ __launch_bounds__(256) void split_kernel(
    const float* __restrict__ s, __half* __restrict__ hi,
    __half* __restrict__ lo, int n4)
{
    int i = blockIdx.x * blockDim.x + threadIdx.x;
    if (i >= n4) return;
    float4 v = ((const float4*)s)[i];
    uint32_t h0, l0, h1, l1;
    split_pack_h(v.x, v.y, h0, l0);
    split_pack_h(v.z, v.w, h1, l1);
    ((uint32_t*)hi)[2 * i]     = h0;
    ((uint32_t*)hi)[2 * i + 1] = h1;
    ((uint32_t*)lo)[2 * i]     = l0;
    ((uint32_t*)lo)[2 * i + 1] = l1;
}

// fp32 -> fp16 hi only
__global__ __launch_bounds__(256) void tohalf_kernel(
    const float* __restrict__ s, __half* __restrict__ hi, int n4)
{
    int i = blockIdx.x * blockDim.x + threadIdx.x;
    if (i >= n4) return;
    float4 v = ((const float4*)s)[i];
    ((uint32_t*)hi)[2 * i]     = pack_h2(v.x, v.y);
    ((uint32_t*)hi)[2 * i + 1] = pack_h2(v.z, v.w);
}

// ---------------------------------------------------------------------------
// fp16 GEMM via mma.sync:  D[128x128] = A[128xK] @ B[128xK]^T
// MODE 0 (QKV): 1-term Ah·Bh; epilogue writes qh/kh/vh.
// MODE 1 (proj): 3-term (Ah+Al)·Bh + Ah·Bl; out = D + bias (fp32).
// 256 threads (8 warps: 4 M x 2 N), warp tile 32x64, K-chunk 32, 2-stage,
// SW64-swizzled 64B smem rows. 2 CTAs/SM.
// ---------------------------------------------------------------------------
template <int MODE>
__global__ __launch_bounds__(256, 2) void mma_gemm(
    const __half* __restrict__ Ah, const __half* __restrict__ Al,
    const __half* __restrict__ Bh, const __half* __restrict__ Bl,
    const float* __restrict__ bias, float* __restrict__ out)
{
    constexpr int TILE   = 128 * 64;          // 8192 B
    constexpr int NTILES = (MODE == 0) ? 2 : 4;
    constexpr int STAGE  = NTILES * TILE;
    constexpr int NCH    = KKG / 32;          // 16 K-chunks

    extern __shared__ char dsm[];
    const uint32_t sbase = smem_u32(dsm);

    const int tid  = threadIdx.x;
    const int lane = tid & 31;
    const int wid  = tid >> 5;
    const int mw   = wid & 3;                 // 0..3 -> M groups of 32
    const int nw   = wid >> 2;                // 0..1 -> N groups of 64
    const int rowBase = blockIdx.y * 128;
    const int colBase = blockIdx.x * 128;

    float acc[2][8][4];
    #pragma unroll
    for (int a = 0; a < 2; a++)
        #pragma unroll
        for (int b = 0; b < 8; b++)
            #pragma unroll
            for (int c = 0; c < 4; c++) acc[a][b][c] = 0.0f;

    const int aRow  = mw * 32 + (lane & 15);
    const int aSeg0 = lane >> 4;
    const int bRow  = nw * 64 + ((lane >> 4) & 1) * 8 + (lane & 7);
    const int bSeg0 = (lane >> 3) & 1;

    auto loadChunk = [&](int ch, int buf) {
        const uint32_t sb = sbase + buf * STAGE;
        #pragma unroll
        for (int rep = 0; rep < 2; rep++) {
            const int id  = tid * 2 + rep;
            const int r   = id >> 2;
            const int seg = id & 3;
            const uint32_t so = sw64(r, seg);
            const size_t  ga = (size_t)(rowBase + r) * KKG + ch * 32 + seg * 8;
            const size_t  gb = (size_t)(colBase + r) * KKG + ch * 32 + seg * 8;
            if (MODE == 0) {
                cp_async16(sb + so,        Ah + ga);
                cp_async16(sb + TILE + so, Bh + gb);
            } else {
                cp_async16(sb + so,            Ah + ga);
                cp_async16(sb + TILE + so,     Al + ga);
                cp_async16(sb + 2 * TILE + so, Bh + gb);
                cp_async16(sb + 3 * TILE + so, Bl + gb);
            }
        }
    };

    loadChunk(0, 0);
    CP_COMMIT();

    for (int ch = 0; ch < NCH; ch++) {
        if (ch + 1 < NCH) {
            loadChunk(ch + 1, (ch + 1) & 1);
            CP_COMMIT();
            CP_WAIT1();
        } else {
            CP_WAIT0();
        }
        __syncthreads();

        const uint32_t st = sbase + (ch & 1) * STAGE;
        const uint32_t bOffTile = (MODE == 0) ? TILE : 2 * TILE;
        #pragma unroll
        for (int ks = 0; ks < 2; ks++) {
            uint32_t ah[2][4], al[2][4], bb[4][4];
            #pragma unroll
            for (int mm = 0; mm < 2; mm++) {
                const uint32_t ad = st + sw64(aRow + mm * 16, aSeg0 + 2 * ks);
                LDSM_X4(ah[mm], ad);
                if (MODE == 1) LDSM_X4(al[mm], ad + TILE);
            }
            #pragma unroll
            for (int nb = 0; nb < 4; nb++)
                LDSM_X4(bb[nb], st + bOffTile + sw64(bRow + nb * 16, bSeg0 + 2 * ks));

            #pragma unroll
            for (int mm = 0; mm < 2; mm++)
                #pragma unroll
                for (int nf = 0; nf < 8; nf++) {
                    const uint32_t b0 = bb[nf >> 1][(nf & 1) * 2];
                    const uint32_t b1 = bb[nf >> 1][(nf & 1) * 2 + 1];
                    MMA16816(acc[mm][nf], ah[mm], b0, b1);
                    if (MODE == 1) MMA16816(acc[mm][nf], al[mm], b0, b1);
                }

            if (MODE == 1) {
                #pragma unroll
                for (int nb = 0; nb < 4; nb++)
                    LDSM_X4(bb[nb], st + 3 * TILE + sw64(bRow + nb * 16, bSeg0 + 2 * ks));

                #pragma unroll
                for (int mm = 0; mm < 2; mm++)
                    #pragma unroll
                    for (int nf = 0; nf < 8; nf++) {
                        const uint32_t b0 = bb[nf >> 1][(nf & 1) * 2];
                        const uint32_t b1 = bb[nf >> 1][(nf & 1) * 2 + 1];
                        MMA16816(acc[mm][nf], ah[mm], b0, b1);
                    }
            }
        }
        __syncthreads();
    }

    // Epilogue. C frag: rows lane/4 (+8), cols (lane%4)*2
    #pragma unroll
    for (int mm = 0; mm < 2; mm++) {
        #pragma unroll
        for (int nf = 0; nf < 8; nf++) {
            const int c = colBase + nw * 64 + nf * 8 + (lane & 3) * 2;
            const int r0 = rowBase + mw * 32 + mm * 16 + (lane >> 2);
            if (MODE == 0) {
                const int three = c >> 9;
                const int head  = (c >> 5) & 15;
                const int d     = c & 31;
                __half* dst = (three == 0) ? g_qh : (three == 1) ? g_kh : g_vh;
                #pragma unroll
                for (int half = 0; half < 2; half++) {
                    const int r = r0 + half * 8;
                    const int b = r >> 10, n = r & 1023;
                    const size_t idx = (((size_t)(b * NHEAD + head) * NN) + n) * HD + d;
                    *(uint32_t*)(dst + idx) =
                        pack_h2(acc[mm][nf][half * 2], acc[mm][nf][half * 2 + 1]);
                }
            } else {
                const float2 bv = *(const float2*)(bias + c);
                #pragma unroll
                for (int half = 0; half < 2; half++) {
                    const int r = r0 + half * 8;
                    float2 v = make_float2(acc[mm][nf][half * 2] + bv.x,
                                           acc[mm][nf][half * 2 + 1] + bv.y);
                    *(float2*)(out + (size_t)r * CD + c) = v;
                }
            }
        }
    }
}

// ---------------------------------------------------------------------------
// Tensor-core flash attention (fp16, single-term).
// QK^T: Qh·Kh.  P·V: Ph·Vh.
// 256 thr / 8 warps; 128 q-rows per block, 16 per warp; 64-key tiles,
// 2-stage cp.async, SW64 swizzle. 2 CTAs/SM. grid = (NN/128, NHEAD, BB)
// ---------------------------------------------------------------------------
__global__ __launch_bounds__(256, 2) void attn_mma_kernel(float* __restrict__ y)
{
    constexpr int QBYTES = 128 * 64;          // 8192 (single Q matrix)
    constexpr int TMAT   = 64 * 64;           // 4096 per kv matrix
    constexpr int STAGE  = 2 * TMAT;          // 8192: kh, vh
    constexpr int NT     = NN / 64;           // 16 tiles
    const float C2  = 0.17677669529663687f * 1.44269504088896340736f;  // SC*log2e

    extern __shared__ char dsm[];
    const uint32_t sQH = smem_u32(dsm);
    const uint32_t sKV = sQH + QBYTES;

    const int tid  = threadIdx.x;
    const int lane = tid & 31;
    const int wid  = tid >> 5;
    const int wr   = wid * 16;

    const int b = blockIdx.z;
    const int h = blockIdx.y;
    const int rowBase = blockIdx.x * 128;
    const size_t hb = ((size_t)(b * NHEAD + h)) * NN * HD;

    auto loadKV = [&](int t, int buf) {
        const uint32_t sb = sKV + buf * STAGE;
        const int row = tid >> 2, seg = tid & 3;
        const uint32_t so = sw64(row, seg);
        const size_t g = hb + (size_t)(t * 64 + row) * HD + seg * 8;
        cp_async16(sb + so,        g_kh + g);
        cp_async16(sb + TMAT + so, g_vh + g);
    };

    {   // Q load (single matrix: 128 rows x 4 segs = 512 cp / 256 thr) + KV tile 0
        {
            const int id  = tid * 2;
            const int row = id >> 2, seg = id & 3;
            const size_t g = hb + (size_t)(rowBase + row) * HD + seg * 8;
            cp_async16(sQH + sw64(row, seg),     g_qh + g);
            cp_async16(sQH + sw64(row, seg + 1), g_qh + g + 8);
        }
        loadKV(0, 0);
        CP_COMMIT();
    }

    float acc[4][4];
    #pragma unroll
    for (int a = 0; a < 4; a++)
        #pragma unroll
        for (int c = 0; c < 4; c++) acc[a][c] = 0.0f;
    float m0 = -1e30f, m1 = -1e30f, l0 = 0.0f, l1 = 0.0f;

    uint32_t qh[2][4];
    const int qRow = wr + (lane & 15);
    const int qSeg0 = lane >> 4;
    const int kRowL = lane & 7;               // + j*8
    const int kSeg = lane >> 3;
    const int vRowL = ((lane >> 3) & 1) * 8 + (lane & 7);   // + kk*16
    const int vSeg0 = lane >> 4;              // + 2*dp

    for (int t = 0; t < NT; t++) {
        if (t + 1 < NT) {
            loadKV(t + 1, (t + 1) & 1);
            CP_COMMIT();
            CP_WAIT1();
        } else {
            CP_WAIT0();
        }
        __syncthreads();

        if (t == 0) {
            #pragma unroll
            for (int kt = 0; kt < 2; kt++)
                LDSM_X4(qh[kt], sQH + sw64(qRow, qSeg0 + 2 * kt));
        }

        const uint32_t st = sKV + (t & 1) * STAGE;

        // ---- scores: S = Qh·Kh^T ----
        float s[8][4];
        #pragma unroll
        for (int j = 0; j < 8; j++) {
            uint32_t kf[4];
            LDSM_X4(kf, st + sw64(j * 8 + kRowL, kSeg));
            s[j][0] = s[j][1] = s[j][2] = s[j][3] = 0.0f;
            MMA16816(s[j], qh[0], kf[0], kf[1]);
            MMA16816(s[j], qh[1], kf[2], kf[3]);
        }

        // ---- online softmax (exp2 with folded scale) ----
        float mx0 = -1e30f, mx1 = -1e30f;
        #pragma unroll
        for (int j = 0; j < 8; j++) {
            mx0 = fmaxf(mx0, fmaxf(s[j][0], s[j][1]));
            mx1 = fmaxf(mx1, fmaxf(s[j][2], s[j][3]));
        }
        mx0 = fmaxf(mx0, __shfl_xor_sync(0xffffffffu, mx0, 1));
        mx0 = fmaxf(mx0, __shfl_xor_sync(0xffffffffu, mx0, 2));
        mx1 = fmaxf(mx1, __shfl_xor_sync(0xffffffffu, mx1, 1));
        mx1 = fmaxf(mx1, __shfl_xor_sync(0xffffffffu, mx1, 2));
        const float nm0 = fmaxf(m0, mx0), nm1 = fmaxf(m1, mx1);
        const float cf0 = ex2((m0 - nm0) * C2);
        const float cf1 = ex2((m1 - nm1) * C2);
        m0 = nm0; m1 = nm1;
        const float ms0 = nm0 * C2, ms1 = nm1 * C2;
        float ps0 = 0.0f, ps1 = 0.0f;
        #pragma unroll
        for (int j = 0; j < 8; j++) {
            s[j][0] = ex2(fmaf(s[j][0], C2, -ms0));
            s[j][1] = ex2(fmaf(s[j][1], C2, -ms0));
            s[j][2] = ex2(fmaf(s[j][2], C2, -ms1));
            s[j][3] = ex2(fmaf(s[j][3], C2, -ms1));
            ps0 += s[j][0] + s[j][1];
            ps1 += s[j][2] + s[j][3];
        }
        l0 = l0 * cf0 + ps0;
        l1 = l1 * cf1 + ps1;
        #pragma unroll
        for (int a = 0; a < 4; a++) {
            acc[a][0] *= cf0; acc[a][1] *= cf0;
            acc[a][2] *= cf1; acc[a][3] *= cf1;
        }

        // ---- P·V: Ph·Vh ----
        #pragma unroll
        for (int kk = 0; kk < 4; kk++) {
            uint32_t ph[4];
            ph[0] = pack_h2(s[2 * kk][0],     s[2 * kk][1]);
            ph[1] = pack_h2(s[2 * kk][2],     s[2 * kk][3]);
            ph[2] = pack_h2(s[2 * kk + 1][0], s[2 * kk + 1][1]);
            ph[3] = pack_h2(s[2 * kk + 1][2], s[2 * kk + 1][3]);
            #pragma unroll
            for (int dp = 0; dp < 2; dp++) {
                uint32_t vh[4];
                LDSM_X4_T(vh, st + TMAT + sw64(kk * 16 + vRowL, vSeg0 + 2 * dp));
                MMA16816(acc[2 * dp],     ph, vh[0], vh[1]);
                MMA16816(acc[2 * dp + 1], ph, vh[2], vh[3]);
            }
        }
        __syncthreads();
    }

    l0 += __shfl_xor_sync(0xffffffffu, l0, 1);
    l0 += __shfl_xor_sync(0xffffffffu, l0, 2);
    l1 += __shfl_xor_sync(0xffffffffu, l1, 1);
    l1 += __shfl_xor_sync(0xffffffffu, l1, 2);
    const float inv0 = 1.0f / l0, inv1 = 1.0f / l1;

    const int r0 = rowBase + wr + (lane >> 2);
    const int cB = h * HD + (lane & 3) * 2;
    #pragma unroll
    for (int dn = 0; dn < 4; dn++) {
        *(float2*)(y + (size_t)(b * NN + r0) * CD + cB + dn * 8) =
            make_float2(acc[dn][0] * inv0, acc[dn][1] * inv0);
        *(float2*)(y + (size_t)(b * NN + r0 + 8) * CD + cB + dn * 8) =
            make_float2(acc[dn][2] * inv1, acc[dn][3] * inv1);
    }
}

// ---------------------------------------------------------------------------
// Fused LePE + split: yh/yl = split( y_attn + dwconv5x5(x) + bias ), fp16
// grid = (W, H, B), block = 128 threads (4 channels each)
// ---------------------------------------------------------------------------
__global__ __launch_bounds__(128) void lepe_split_kernel(
    const float* __restrict__ x, const float* __restrict__ wl,
    const float* __restrict__ bl, const float* __restrict__ y,
    __half* __restrict__ yh, __half* __restrict__ yl)
{
    const int b  = blockIdx.z;
    const int yy = blockIdx.y;
    const int xx = blockIdx.x;
    const int c  = threadIdx.x * 4;

    float4 sum = *(const float4*)&bl[c];
    #pragma unroll
    for (int ky = 0; ky < 5; ky++) {
        const int iy = yy + ky - 2;
        if (iy < 0 || iy >= HH) continue;
        #pragma unroll
        for (int kx = 0; kx < 5; kx++) {
            const int ix = xx + kx - 2;
            if (ix < 0 || ix >= WWI) continue;
            const float4 xv = *(const float4*)&x[(((size_t)(b * HH + iy) * WWI + ix) * CD) + c];
            const int wk = ky * 5 + kx;
            sum.x = fmaf(xv.x, wl[(c + 0) * 25 + wk], sum.x);
            sum.y = fmaf(xv.y, wl[(c + 1) * 25 + wk], sum.y);
            sum.z = fmaf(xv.z, wl[(c + 2) * 25 + wk], sum.z);
            sum.w = fmaf(xv.w, wl[(c + 3) * 25 + wk], sum.w);
        }
    }
    const size_t idx = (((size_t)b * NN + yy * WWI + xx) * CD) + c;
    const float4 av = *(const float4*)&y[idx];
    sum.x += av.x; sum.y += av.y; sum.z += av.z; sum.w += av.w;
    uint32_t h0, l0, h1, l1;
    split_pack_h(sum.x, sum.y, h0, l0);
    split_pack_h(sum.z, sum.w, h1, l1);
    uint32_t* H = (uint32_t*)(yh + idx);
    uint32_t* L = (uint32_t*)(yl + idx);
    H[0] = h0; H[1] = h1;
    L[0] = l0; L[1] = l1;
}

// ---------------------------------------------------------------------------
extern "C" void kernel_launch(void* const* d_in, const int* in_sizes, int n_in,
                              void* d_out, int out_size)
{
    const float* x      = (const float*)d_in[0];
    const float* w_qkv  = (const float*)d_in[1];
    const float* w_proj = (const float*)d_in[2];
    const float* b_proj = (const float*)d_in[3];
    const float* w_lepe = (const float*)d_in[4];
    const float* b_lepe = (const float*)d_in[5];
    float* out = (float*)d_out;

    float *yPtr;
    __half *xh, *yh, *yl, *wqh, *wph, *wpl;
    cudaGetSymbolAddress((void**)&yPtr, g_y);
    cudaGetSymbolAddress((void**)&xh, g_xh);
    cudaGetSymbolAddress((void**)&yh, g_yh);   cudaGetSymbolAddress((void**)&yl, g_yl);
    cudaGetSymbolAddress((void**)&wqh, g_wqh);
    cudaGetSymbolAddress((void**)&wph, g_wph); cudaGetSymbolAddress((void**)&wpl, g_wpl);

    constexpr int SMEM_GEMM0 = 2 * 2 * 128 * 64;               // 32768 B (2 tiles)
    constexpr int SMEM_GEMM1 = 2 * 4 * 128 * 64;               // 65536 B (4 tiles)
    constexpr int SMEM_ATTN  = 128 * 64 + 2 * 2 * 64 * 64;     // 8192 + 16384 = 24576 B
    cudaFuncSetAttribute(mma_gemm<0>, cudaFuncAttributeMaxDynamicSharedMemorySize, SMEM_GEMM0);
    cudaFuncSetAttribute(mma_gemm<1>, cudaFuncAttributeMaxDynamicSharedMemorySize, SMEM_GEMM1);
    cudaFuncSetAttribute(attn_mma_kernel, cudaFuncAttributeMaxDynamicSharedMemorySize, SMEM_ATTN);

    // 0) convert inputs/weights to fp16
    {
        int n4 = MTOT * CD / 4;
        tohalf_kernel<<<(n4 + 255) / 256, 256>>>(x, xh, n4);
        int w4 = 3 * CD * CD / 4;
        tohalf_kernel<<<(w4 + 255) / 256, 256>>>(w_qkv, wqh, w4);
        int p4 = CD * CD / 4;
        split_kernel<<<(p4 + 255) / 256, 256>>>(w_proj, wph, wpl, p4);
    }
    // 1) QKV projection -> g_qh, g_kh, g_vh   (M=8192, N=1536, K=512)
    {
        dim3 grid(3 * CD / 128, MTOT / 128);
        mma_gemm<0><<<grid, 256, SMEM_GEMM0>>>(xh, nullptr, wqh, nullptr, nullptr, nullptr);
    }
    // 2) Attention -> g_y (fp32)
    {
        dim3 grid(NN / 128, NHEAD, BB);
        attn_mma_kernel<<<grid, 256, SMEM_ATTN>>>(yPtr);
    }
    // 3) Fused LePE + split -> g_yh/g_yl
    {
        dim3 grid(WWI, HH, BB);
        lepe_split_kernel<<<grid, 128>>>(x, w_lepe, b_lepe, yPtr, yh, yl);
    }
    // 4) Output projection -> d_out  (M=8192, N=512, K=512)
    {
        dim3 grid(CD / 128, MTOT / 128);
        mma_gemm<1><<<grid, 256, SMEM_GEMM1>>>(yh, yl, wph, wpl, b_proj, out);
    }
}

// round 16
// speedup vs baseline: 1.6774x; 1.0933x over previous
#include <cuda_runtime.h>
#include <cuda_fp16.h>
#include <cstdint>

// Problem constants
constexpr int BB    = 8;      // batch
constexpr int HH    = 32;     // height
constexpr int WWI   = 32;     // width
constexpr int NN    = 1024;   // tokens = H*W
constexpr int CD    = 512;    // dim
constexpr int NHEAD = 16;
constexpr int HD    = 32;     // head dim
constexpr int MTOT  = BB * NN;   // 8192 rows
constexpr int KKG   = 512;       // GEMM K (both GEMMs)

// ---------------------------------------------------------------------------
// Scratch (device globals; no allocation allowed) — fp16 single-term scheme
// ---------------------------------------------------------------------------
__device__ float g_y[MTOT * CD];                    // attn out (fp32)
__device__ __half g_xh[MTOT * CD];                  // x fp16
__device__ __half g_yh[MTOT * CD];                  // (attn + lepe) fp16
__device__ __half g_wqh[3 * CD * CD];               // qkv weight fp16
__device__ __half g_wph[CD * CD];                   // proj weight fp16
// Q/K/V fp16, layout [(b*NHEAD+h)][N][HD]
constexpr int QKV_ELEMS = BB * NHEAD * NN * HD;
__device__ __half g_qh[QKV_ELEMS], g_kh[QKV_ELEMS], g_vh[QKV_ELEMS];

// ---------------------------------------------------------------------------
// PTX helpers — sm_103-base ISA only (NO tcgen05: harness PTX targets sm_103)
// ---------------------------------------------------------------------------
__device__ __forceinline__ uint32_t smem_u32(const void* p) {
    uint32_t a;
    asm("{ .reg .u64 t; cvta.to.shared.u64 t, %1; cvt.u32.u64 %0, t; }" : "=r"(a) : "l"(p));
    return a;
}

__device__ __forceinline__ void cp_async16(uint32_t s, const void* g) {
    asm volatile("cp.async.cg.shared.global [%0], [%1], 16;" :: "r"(s), "l"(g));
}

#define CP_COMMIT() asm volatile("cp.async.commit_group;")
#define CP_WAIT1()  asm volatile("cp.async.wait_group 1;")
#define CP_WAIT0()  asm volatile("cp.async.wait_group 0;")

#define LDSM_X4(R, addr)                                                     \
    asm volatile("ldmatrix.sync.aligned.m8n8.x4.shared.b16 {%0,%1,%2,%3}, [%4];" \
        : "=r"((R)[0]), "=r"((R)[1]), "=r"((R)[2]), "=r"((R)[3]) : "r"(addr))

#define LDSM_X4_T(R, addr)                                                   \
    asm volatile("ldmatrix.sync.aligned.m8n8.x4.trans.shared.b16 {%0,%1,%2,%3}, [%4];" \
        : "=r"((R)[0]), "=r"((R)[1]), "=r"((R)[2]), "=r"((R)[3]) : "r"(addr))

// fp16 in / fp32 accumulate
#define MMA16816(C, A, B0, B1)                                               \
    asm volatile("mma.sync.aligned.m16n8k16.row.col.f32.f16.f16.f32 "        \
        "{%0,%1,%2,%3}, {%4,%5,%6,%7}, {%8,%9}, {%0,%1,%2,%3};"              \
        : "+f"((C)[0]), "+f"((C)[1]), "+f"((C)[2]), "+f"((C)[3])             \
        : "r"((A)[0]), "r"((A)[1]), "r"((A)[2]), "r"((A)[3]),                \
          "r"(B0), "r"(B1))

__device__ __forceinline__ float ex2(float x) {
    float r;
    asm("ex2.approx.f32 %0, %1;" : "=f"(r) : "f"(x));
    return r;
}

// SW64 swizzle: 64B rows, 16B segments; conflict-free for ldmatrix + cp.async
__device__ __forceinline__ uint32_t sw64(int row, int seg) {
    return (uint32_t)(row * 64 + ((seg ^ ((row >> 1) & 3)) << 4));
}

__device__ __forceinline__ uint32_t pack_h2(float a, float b) {
    __half2 h = __floats2half2_rn(a, b);
    uint32_t r;
    memcpy(&r, &h, 4);
    return r;
}

// ---------------------------------------------------------------------------
// fp32 -> fp16; float4 per thread
// ---------------------------------------------------------------------------
__global__ __launch_bounds__(256) void tohalf_kernel(
    const float* __restrict__ s, __half* __restrict__ hi, int n4)
{
    int i = blockIdx.x * blockDim.x + threadIdx.x;
    if (i >= n4) return;
    float4 v = ((const float4*)s)[i];
    ((uint32_t*)hi)[2 * i]     = pack_h2(v.x, v.y);
    ((uint32_t*)hi)[2 * i + 1] = pack_h2(v.z, v.w);
}

// ---------------------------------------------------------------------------
// fp16 single-term GEMM via mma.sync:  D[128x128] = A[128xK] @ B[128xK]^T
// MODE 0 (QKV): epilogue scatters qh/kh/vh.  MODE 1 (proj): out = D + bias.
// 256 threads (8 warps: 4 M x 2 N), warp tile 32x64, K-chunk 32, 2-stage,
// SW64-swizzled 64B smem rows. 2 CTAs/SM.
// ---------------------------------------------------------------------------
template <int MODE>
__global__ __launch_bounds__(256, 2) void mma_gemm(
    const __half* __restrict__ Ah, const __half* __restrict__ Bh,
    const float* __restrict__ bias, float* __restrict__ out)
{
    constexpr int TILE  = 128 * 64;           // 8192 B
    constexpr int STAGE = 2 * TILE;           // A, B
    constexpr int NCH   = KKG / 32;           // 16 K-chunks

    extern __shared__ char dsm[];
    const uint32_t sbase = smem_u32(dsm);

    const int tid  = threadIdx.x;
    const int lane = tid & 31;
    const int wid  = tid >> 5;
    const int mw   = wid & 3;                 // 0..3 -> M groups of 32
    const int nw   = wid >> 2;                // 0..1 -> N groups of 64
    const int rowBase = blockIdx.y * 128;
    const int colBase = blockIdx.x * 128;

    float acc[2][8][4];
    #pragma unroll
    for (int a = 0; a < 2; a++)
        #pragma unroll
        for (int b = 0; b < 8; b++)
            #pragma unroll
            for (int c = 0; c < 4; c++) acc[a][b][c] = 0.0f;

    const int aRow  = mw * 32 + (lane & 15);
    const int aSeg0 = lane >> 4;
    const int bRow  = nw * 64 + ((lane >> 4) & 1) * 8 + (lane & 7);
    const int bSeg0 = (lane >> 3) & 1;

    auto loadChunk = [&](int ch, int buf) {
        const uint32_t sb = sbase + buf * STAGE;
        #pragma unroll
        for (int rep = 0; rep < 2; rep++) {
            const int id  = tid * 2 + rep;
            const int r   = id >> 2;
            const int seg = id & 3;
            const uint32_t so = sw64(r, seg);
            const size_t  ga = (size_t)(rowBase + r) * KKG + ch * 32 + seg * 8;
            const size_t  gb = (size_t)(colBase + r) * KKG + ch * 32 + seg * 8;
            cp_async16(sb + so,        Ah + ga);
            cp_async16(sb + TILE + so, Bh + gb);
        }
    };

    loadChunk(0, 0);
    CP_COMMIT();

    for (int ch = 0; ch < NCH; ch++) {
        if (ch + 1 < NCH) {
            loadChunk(ch + 1, (ch + 1) & 1);
            CP_COMMIT();
            CP_WAIT1();
        } else {
            CP_WAIT0();
        }
        __syncthreads();

        const uint32_t st = sbase + (ch & 1) * STAGE;
        #pragma unroll
        for (int ks = 0; ks < 2; ks++) {
            uint32_t ah[2][4], bb[4][4];
            #pragma unroll
            for (int mm = 0; mm < 2; mm++)
                LDSM_X4(ah[mm], st + sw64(aRow + mm * 16, aSeg0 + 2 * ks));
            #pragma unroll
            for (int nb = 0; nb < 4; nb++)
                LDSM_X4(bb[nb], st + TILE + sw64(bRow + nb * 16, bSeg0 + 2 * ks));

            #pragma unroll
            for (int mm = 0; mm < 2; mm++)
                #pragma unroll
                for (int nf = 0; nf < 8; nf++) {
                    const uint32_t b0 = bb[nf >> 1][(nf & 1) * 2];
                    const uint32_t b1 = bb[nf >> 1][(nf & 1) * 2 + 1];
                    MMA16816(acc[mm][nf], ah[mm], b0, b1);
                }
        }
        __syncthreads();
    }

    // Epilogue. C frag: rows lane/4 (+8), cols (lane%4)*2
    #pragma unroll
    for (int mm = 0; mm < 2; mm++) {
        #pragma unroll
        for (int nf = 0; nf < 8; nf++) {
            const int c = colBase + nw * 64 + nf * 8 + (lane & 3) * 2;
            const int r0 = rowBase + mw * 32 + mm * 16 + (lane >> 2);
            if (MODE == 0) {
                const int three = c >> 9;
                const int head  = (c >> 5) & 15;
                const int d     = c & 31;
                __half* dst = (three == 0) ? g_qh : (three == 1) ? g_kh : g_vh;
                #pragma unroll
                for (int half = 0; half < 2; half++) {
                    const int r = r0 + half * 8;
                    const int b = r >> 10, n = r & 1023;
                    const size_t idx = (((size_t)(b * NHEAD + head) * NN) + n) * HD + d;
                    *(uint32_t*)(dst + idx) =
                        pack_h2(acc[mm][nf][half * 2], acc[mm][nf][half * 2 + 1]);
                }
            } else {
                const float2 bv = *(const float2*)(bias + c);
                #pragma unroll
                for (int half = 0; half < 2; half++) {
                    const int r = r0 + half * 8;
                    float2 v = make_float2(acc[mm][nf][half * 2] + bv.x,
                                           acc[mm][nf][half * 2 + 1] + bv.y);
                    *(float2*)(out + (size_t)r * CD + c) = v;
                }
            }
        }
    }
}

// ---------------------------------------------------------------------------
// Tensor-core flash attention (fp16, single-term).
// QK^T: Qh·Kh.  P·V: Ph·Vh.
// 256 thr / 8 warps; 128 q-rows per block, 16 per warp; 64-key tiles,
// 2-stage cp.async, SW64 swizzle. 2 CTAs/SM. grid = (NN/128, NHEAD, BB)
// ---------------------------------------------------------------------------
__global__ __launch_bounds__(256, 2) void attn_mma_kernel(float* __restrict__ y)
{
    constexpr int QBYTES = 128 * 64;          // 8192 (single Q matrix)
    constexpr int TMAT   = 64 * 64;           // 4096 per kv matrix
    constexpr int STAGE  = 2 * TMAT;          // 8192: kh, vh
    constexpr int NT     = NN / 64;           // 16 tiles
    const float C2  = 0.17677669529663687f * 1.44269504088896340736f;  // SC*log2e

    extern __shared__ char dsm[];
    const uint32_t sQH = smem_u32(dsm);
    const uint32_t sKV = sQH + QBYTES;

    const int tid  = threadIdx.x;
    const int lane = tid & 31;
    const int wid  = tid >> 5;
    const int wr   = wid * 16;

    const int b = blockIdx.z;
    const int h = blockIdx.y;
    const int rowBase = blockIdx.x * 128;
    const size_t hb = ((size_t)(b * NHEAD + h)) * NN * HD;

    auto loadKV = [&](int t, int buf) {
        const uint32_t sb = sKV + buf * STAGE;
        const int row = tid >> 2, seg = tid & 3;
        const uint32_t so = sw64(row, seg);
        const size_t g = hb + (size_t)(t * 64 + row) * HD + seg * 8;
        cp_async16(sb + so,        g_kh + g);
        cp_async16(sb + TMAT + so, g_vh + g);
    };

    {   // Q load (single matrix: 128 rows x 4 segs = 512 cp / 256 thr) + KV tile 0
        {
            const int id  = tid * 2;
            const int row = id >> 2, seg = id & 3;
            const size_t g = hb + (size_t)(rowBase + row) * HD + seg * 8;
            cp_async16(sQH + sw64(row, seg),     g_qh + g);
            cp_async16(sQH + sw64(row, seg + 1), g_qh + g + 8);
        }
        loadKV(0, 0);
        CP_COMMIT();
    }

    float acc[4][4];
    #pragma unroll
    for (int a = 0; a < 4; a++)
        #pragma unroll
        for (int c = 0; c < 4; c++) acc[a][c] = 0.0f;
    float m0 = -1e30f, m1 = -1e30f, l0 = 0.0f, l1 = 0.0f;

    uint32_t qh[2][4];
    const int qRow = wr + (lane & 15);
    const int qSeg0 = lane >> 4;
    const int kRowL = lane & 7;               // + j*8
    const int kSeg = lane >> 3;
    const int vRowL = ((lane >> 3) & 1) * 8 + (lane & 7);   // + kk*16
    const int vSeg0 = lane >> 4;              // + 2*dp

    for (int t = 0; t < NT; t++) {
        if (t + 1 < NT) {
            loadKV(t + 1, (t + 1) & 1);
            CP_COMMIT();
            CP_WAIT1();
        } else {
            CP_WAIT0();
        }
        __syncthreads();

        if (t == 0) {
            #pragma unroll
            for (int kt = 0; kt < 2; kt++)
                LDSM_X4(qh[kt], sQH + sw64(qRow, qSeg0 + 2 * kt));
        }

        const uint32_t st = sKV + (t & 1) * STAGE;

        // ---- scores: S = Qh·Kh^T ----
        float s[8][4];
        #pragma unroll
        for (int j = 0; j < 8; j++) {
            uint32_t kf[4];
            LDSM_X4(kf, st + sw64(j * 8 + kRowL, kSeg));
            s[j][0] = s[j][1] = s[j][2] = s[j][3] = 0.0f;
            MMA16816(s[j], qh[0], kf[0], kf[1]);
            MMA16816(s[j], qh[1], kf[2], kf[3]);
        }

        // ---- online softmax (exp2 with folded scale) ----
        float mx0 = -1e30f, mx1 = -1e30f;
        #pragma unroll
        for (int j = 0; j < 8; j++) {
            mx0 = fmaxf(mx0, fmaxf(s[j][0], s[j][1]));
            mx1 = fmaxf(mx1, fmaxf(s[j][2], s[j][3]));
        }
        mx0 = fmaxf(mx0, __shfl_xor_sync(0xffffffffu, mx0, 1));
        mx0 = fmaxf(mx0, __shfl_xor_sync(0xffffffffu, mx0, 2));
        mx1 = fmaxf(mx1, __shfl_xor_sync(0xffffffffu, mx1, 1));
        mx1 = fmaxf(mx1, __shfl_xor_sync(0xffffffffu, mx1, 2));
        const float nm0 = fmaxf(m0, mx0), nm1 = fmaxf(m1, mx1);
        const float cf0 = ex2((m0 - nm0) * C2);
        const float cf1 = ex2((m1 - nm1) * C2);
        m0 = nm0; m1 = nm1;
        const float ms0 = nm0 * C2, ms1 = nm1 * C2;
        float ps0 = 0.0f, ps1 = 0.0f;
        #pragma unroll
        for (int j = 0; j < 8; j++) {
            s[j][0] = ex2(fmaf(s[j][0], C2, -ms0));
            s[j][1] = ex2(fmaf(s[j][1], C2, -ms0));
            s[j][2] = ex2(fmaf(s[j][2], C2, -ms1));
            s[j][3] = ex2(fmaf(s[j][3], C2, -ms1));
            ps0 += s[j][0] + s[j][1];
            ps1 += s[j][2] + s[j][3];
        }
        l0 = l0 * cf0 + ps0;
        l1 = l1 * cf1 + ps1;
        #pragma unroll
        for (int a = 0; a < 4; a++) {
            acc[a][0] *= cf0; acc[a][1] *= cf0;
            acc[a][2] *= cf1; acc[a][3] *= cf1;
        }

        // ---- P·V: Ph·Vh ----
        #pragma unroll
        for (int kk = 0; kk < 4; kk++) {
            uint32_t ph[4];
            ph[0] = pack_h2(s[2 * kk][0],     s[2 * kk][1]);
            ph[1] = pack_h2(s[2 * kk][2],     s[2 * kk][3]);
            ph[2] = pack_h2(s[2 * kk + 1][0], s[2 * kk + 1][1]);
            ph[3] = pack_h2(s[2 * kk + 1][2], s[2 * kk + 1][3]);
            #pragma unroll
            for (int dp = 0; dp < 2; dp++) {
                uint32_t vh[4];
                LDSM_X4_T(vh, st + TMAT + sw64(kk * 16 + vRowL, vSeg0 + 2 * dp));
                MMA16816(acc[2 * dp],     ph, vh[0], vh[1]);
                MMA16816(acc[2 * dp + 1], ph, vh[2], vh[3]);
            }
        }
        __syncthreads();
    }

    l0 += __shfl_xor_sync(0xffffffffu, l0, 1);
    l0 += __shfl_xor_sync(0xffffffffu, l0, 2);
    l1 += __shfl_xor_sync(0xffffffffu, l1, 1);
    l1 += __shfl_xor_sync(0xffffffffu, l1, 2);
    const float inv0 = 1.0f / l0, inv1 = 1.0f / l1;

    const int r0 = rowBase + wr + (lane >> 2);
    const int cB = h * HD + (lane & 3) * 2;
    #pragma unroll
    for (int dn = 0; dn < 4; dn++) {
        *(float2*)(y + (size_t)(b * NN + r0) * CD + cB + dn * 8) =
            make_float2(acc[dn][0] * inv0, acc[dn][1] * inv0);
        *(float2*)(y + (size_t)(b * NN + r0 + 8) * CD + cB + dn * 8) =
            make_float2(acc[dn][2] * inv1, acc[dn][3] * inv1);
    }
}

// ---------------------------------------------------------------------------
// Fused LePE + to-fp16: yh = half( y_attn + dwconv5x5(x) + bias )
// grid = (W, H, B), block = 128 threads (4 channels each)
// ---------------------------------------------------------------------------
__global__ __launch_bounds__(128) void lepe_tohalf_kernel(
    const float* __restrict__ x, const float* __restrict__ wl,
    const float* __restrict__ bl, const float* __restrict__ y,
    __half* __restrict__ yh)
{
    const int b  = blockIdx.z;
    const int yy = blockIdx.y;
    const int xx = blockIdx.x;
    const int c  = threadIdx.x * 4;

    float4 sum = *(const float4*)&bl[c];
    #pragma unroll
    for (int ky = 0; ky < 5; ky++) {
        const int iy = yy + ky - 2;
        if (iy < 0 || iy >= HH) continue;
        #pragma unroll
        for (int kx = 0; kx < 5; kx++) {
            const int ix = xx + kx - 2;
            if (ix < 0 || ix >= WWI) continue;
            const float4 xv = *(const float4*)&x[(((size_t)(b * HH + iy) * WWI + ix) * CD) + c];
            const int wk = ky * 5 + kx;
            sum.x = fmaf(xv.x, wl[(c + 0) * 25 + wk], sum.x);
            sum.y = fmaf(xv.y, wl[(c + 1) * 25 + wk], sum.y);
            sum.z = fmaf(xv.z, wl[(c + 2) * 25 + wk], sum.z);
            sum.w = fmaf(xv.w, wl[(c + 3) * 25 + wk], sum.w);
        }
    }
    const size_t idx = (((size_t)b * NN + yy * WWI + xx) * CD) + c;
    const float4 av = *(const float4*)&y[idx];
    uint32_t* H = (uint32_t*)(yh + idx);
    H[0] = pack_h2(sum.x + av.x, sum.y + av.y);
    H[1] = pack_h2(sum.z + av.z, sum.w + av.w);
}

// ---------------------------------------------------------------------------
extern "C" void kernel_launch(void* const* d_in, const int* in_sizes, int n_in,
                              void* d_out, int out_size)
{
    const float* x      = (const float*)d_in[0];
    const float* w_qkv  = (const float*)d_in[1];
    const float* w_proj = (const float*)d_in[2];
    const float* b_proj = (const float*)d_in[3];
    const float* w_lepe = (const float*)d_in[4];
    const float* b_lepe = (const float*)d_in[5];
    float* out = (float*)d_out;

    float *yPtr;
    __half *xh, *yh, *wqh, *wph;
    cudaGetSymbolAddress((void**)&yPtr, g_y);
    cudaGetSymbolAddress((void**)&xh, g_xh);
    cudaGetSymbolAddress((void**)&yh, g_yh);
    cudaGetSymbolAddress((void**)&wqh, g_wqh);
    cudaGetSymbolAddress((void**)&wph, g_wph);

    constexpr int SMEM_GEMM = 2 * 2 * 128 * 64;                // 32768 B
    constexpr int SMEM_ATTN = 128 * 64 + 2 * 2 * 64 * 64;      // 24576 B
    cudaFuncSetAttribute(mma_gemm<0>, cudaFuncAttributeMaxDynamicSharedMemorySize, SMEM_GEMM);
    cudaFuncSetAttribute(mma_gemm<1>, cudaFuncAttributeMaxDynamicSharedMemorySize, SMEM_GEMM);
    cudaFuncSetAttribute(attn_mma_kernel, cudaFuncAttributeMaxDynamicSharedMemorySize, SMEM_ATTN);

    // 0) convert inputs/weights to fp16
    {
        int n4 = MTOT * CD / 4;
        tohalf_kernel<<<(n4 + 255) / 256, 256>>>(x, xh, n4);
        int w4 = 3 * CD * CD / 4;
        tohalf_kernel<<<(w4 + 255) / 256, 256>>>(w_qkv, wqh, w4);
        int p4 = CD * CD / 4;
        tohalf_kernel<<<(p4 + 255) / 256, 256>>>(w_proj, wph, p4);
    }
    // 1) QKV projection -> g_qh, g_kh, g_vh   (M=8192, N=1536, K=512)
    {
        dim3 grid(3 * CD / 128, MTOT / 128);
        mma_gemm<0><<<grid, 256, SMEM_GEMM>>>(xh, wqh, nullptr, nullptr);
    }
    // 2) Attention -> g_y (fp32)
    {
        dim3 grid(NN / 128, NHEAD, BB);
        attn_mma_kernel<<<grid, 256, SMEM_ATTN>>>(yPtr);
    }
    // 3) Fused LePE + to-half -> g_yh
    {
        dim3 grid(WWI, HH, BB);
        lepe_tohalf_kernel<<<grid, 128>>>(x, w_lepe, b_lepe, yPtr, yh);
    }
    // 4) Output projection -> d_out  (M=8192, N=512, K=512)
    {
        dim3 grid(CD / 128, MTOT / 128);
        mma_gemm<1><<<grid, 256, SMEM_GEMM>>>(yh, wph, b_proj, out);
    }
}

// round 17
// speedup vs baseline: 2.8656x; 1.7084x over previous
#include <cuda_runtime.h>
#include <cuda_fp16.h>
#include <cstdint>

// Problem constants
constexpr int BB    = 8;      // batch
constexpr int HH    = 32;     // height
constexpr int WWI   = 32;     // width
constexpr int NN    = 1024;   // tokens = H*W
constexpr int CD    = 512;    // dim
constexpr int NHEAD = 16;
constexpr int HD    = 32;     // head dim
constexpr int MTOT  = BB * NN;   // 8192 rows
constexpr int KKG   = 512;       // GEMM K (both GEMMs)

constexpr float C2F = 0.17677669529663687f * 1.44269504088896340736f;  // scale*log2e

// ---------------------------------------------------------------------------
// Scratch (device globals; no allocation allowed) — fp16 single-term scheme
// ---------------------------------------------------------------------------
__device__ float g_y[MTOT * CD];                    // attn out (fp32)
__device__ __half g_xh[MTOT * CD];                  // x fp16
__device__ __half g_yh[MTOT * CD];                  // (attn + lepe) fp16
__device__ __half g_wqh[3 * CD * CD];               // qkv weight fp16
__device__ __half g_wph[CD * CD];                   // proj weight fp16
// Q/K/V fp16, layout [(b*NHEAD+h)][N][HD]  (Q pre-scaled by C2F)
constexpr int QKV_ELEMS = BB * NHEAD * NN * HD;
__device__ __half g_qh[QKV_ELEMS], g_kh[QKV_ELEMS], g_vh[QKV_ELEMS];

// ---------------------------------------------------------------------------
// PTX helpers — sm_103-base ISA only (NO tcgen05: harness PTX targets sm_103)
// ---------------------------------------------------------------------------
__device__ __forceinline__ uint32_t smem_u32(const void* p) {
    uint32_t a;
    asm("{ .reg .u64 t; cvta.to.shared.u64 t, %1; cvt.u32.u64 %0, t; }" : "=r"(a) : "l"(p));
    return a;
}

__device__ __forceinline__ void cp_async16(uint32_t s, const void* g) {
    asm volatile("cp.async.cg.shared.global [%0], [%1], 16;" :: "r"(s), "l"(g));
}

#define CP_COMMIT() asm volatile("cp.async.commit_group;")
#define CP_WAIT1()  asm volatile("cp.async.wait_group 1;")
#define CP_WAIT0()  asm volatile("cp.async.wait_group 0;")

#define LDSM_X4(R, addr)                                                     \
    asm volatile("ldmatrix.sync.aligned.m8n8.x4.shared.b16 {%0,%1,%2,%3}, [%4];" \
        : "=r"((R)[0]), "=r"((R)[1]), "=r"((R)[2]), "=r"((R)[3]) : "r"(addr))

#define LDSM_X4_T(R, addr)                                                   \
    asm volatile("ldmatrix.sync.aligned.m8n8.x4.trans.shared.b16 {%0,%1,%2,%3}, [%4];" \
        : "=r"((R)[0]), "=r"((R)[1]), "=r"((R)[2]), "=r"((R)[3]) : "r"(addr))

// fp16 in / fp32 accumulate
#define MMA16816(C, A, B0, B1)                                               \
    asm volatile("mma.sync.aligned.m16n8k16.row.col.f32.f16.f16.f32 "        \
        "{%0,%1,%2,%3}, {%4,%5,%6,%7}, {%8,%9}, {%0,%1,%2,%3};"              \
        : "+f"((C)[0]), "+f"((C)[1]), "+f"((C)[2]), "+f"((C)[3])             \
        : "r"((A)[0]), "r"((A)[1]), "r"((A)[2]), "r"((A)[3]),                \
          "r"(B0), "r"(B1))

__device__ __forceinline__ float ex2(float x) {
    float r;
    asm("ex2.approx.f32 %0, %1;" : "=f"(r) : "f"(x));
    return r;
}

// SW64 swizzle: 64B rows, 16B segments; conflict-free for ldmatrix + cp.async
__device__ __forceinline__ uint32_t sw64(int row, int seg) {
    return (uint32_t)(row * 64 + ((seg ^ ((row >> 1) & 3)) << 4));
}

__device__ __forceinline__ uint32_t pack_h2(float a, float b) {
    __half2 h = __floats2half2_rn(a, b);
    uint32_t r;
    memcpy(&r, &h, 4);
    return r;
}

// ---------------------------------------------------------------------------
// fp32 -> fp16; float4 per thread
// ---------------------------------------------------------------------------
__global__ __launch_bounds__(256) void tohalf_kernel(
    const float* __restrict__ s, __half* __restrict__ hi, int n4)
{
    int i = blockIdx.x * blockDim.x + threadIdx.x;
    if (i >= n4) return;
    float4 v = ((const float4*)s)[i];
    ((uint32_t*)hi)[2 * i]     = pack_h2(v.x, v.y);
    ((uint32_t*)hi)[2 * i + 1] = pack_h2(v.z, v.w);
}

// ---------------------------------------------------------------------------
// fp16 single-term GEMM via mma.sync:  D[128x128] = A[128xK] @ B[128xK]^T
// MODE 0 (QKV): epilogue scatters qh (pre-scaled by C2F) / kh / vh.
// MODE 1 (proj): out = D + bias (fp32).
// 256 threads (8 warps: 4 M x 2 N), warp tile 32x64, K-chunk 32, 2-stage,
// SW64-swizzled 64B smem rows. 2 CTAs/SM.
// ---------------------------------------------------------------------------
template <int MODE>
__global__ __launch_bounds__(256, 2) void mma_gemm(
    const __half* __restrict__ Ah, const __half* __restrict__ Bh,
    const float* __restrict__ bias, float* __restrict__ out)
{
    constexpr int TILE  = 128 * 64;           // 8192 B
    constexpr int STAGE = 2 * TILE;           // A, B
    constexpr int NCH   = KKG / 32;           // 16 K-chunks

    extern __shared__ char dsm[];
    const uint32_t sbase = smem_u32(dsm);

    const int tid  = threadIdx.x;
    const int lane = tid & 31;
    const int wid  = tid >> 5;
    const int mw   = wid & 3;                 // 0..3 -> M groups of 32
    const int nw   = wid >> 2;                // 0..1 -> N groups of 64
    const int rowBase = blockIdx.y * 128;
    const int colBase = blockIdx.x * 128;

    float acc[2][8][4];
    #pragma unroll
    for (int a = 0; a < 2; a++)
        #pragma unroll
        for (int b = 0; b < 8; b++)
            #pragma unroll
            for (int c = 0; c < 4; c++) acc[a][b][c] = 0.0f;

    const int aRow  = mw * 32 + (lane & 15);
    const int aSeg0 = lane >> 4;
    const int bRow  = nw * 64 + ((lane >> 4) & 1) * 8 + (lane & 7);
    const int bSeg0 = (lane >> 3) & 1;

    auto loadChunk = [&](int ch, int buf) {
        const uint32_t sb = sbase + buf * STAGE;
        #pragma unroll
        for (int rep = 0; rep < 2; rep++) {
            const int id  = tid * 2 + rep;
            const int r   = id >> 2;
            const int seg = id & 3;
            const uint32_t so = sw64(r, seg);
            const size_t  ga = (size_t)(rowBase + r) * KKG + ch * 32 + seg * 8;
            const size_t  gb = (size_t)(colBase + r) * KKG + ch * 32 + seg * 8;
            cp_async16(sb + so,        Ah + ga);
            cp_async16(sb + TILE + so, Bh + gb);
        }
    };

    loadChunk(0, 0);
    CP_COMMIT();

    for (int ch = 0; ch < NCH; ch++) {
        if (ch + 1 < NCH) {
            loadChunk(ch + 1, (ch + 1) & 1);
            CP_COMMIT();
            CP_WAIT1();
        } else {
            CP_WAIT0();
        }
        __syncthreads();

        const uint32_t st = sbase + (ch & 1) * STAGE;
        #pragma unroll
        for (int ks = 0; ks < 2; ks++) {
            uint32_t ah[2][4], bb[4][4];
            #pragma unroll
            for (int mm = 0; mm < 2; mm++)
                LDSM_X4(ah[mm], st + sw64(aRow + mm * 16, aSeg0 + 2 * ks));
            #pragma unroll
            for (int nb = 0; nb < 4; nb++)
                LDSM_X4(bb[nb], st + TILE + sw64(bRow + nb * 16, bSeg0 + 2 * ks));

            #pragma unroll
            for (int mm = 0; mm < 2; mm++)
                #pragma unroll
                for (int nf = 0; nf < 8; nf++) {
                    const uint32_t b0 = bb[nf >> 1][(nf & 1) * 2];
                    const uint32_t b1 = bb[nf >> 1][(nf & 1) * 2 + 1];
                    MMA16816(acc[mm][nf], ah[mm], b0, b1);
                }
        }
        __syncthreads();
    }

    // Epilogue. C frag: rows lane/4 (+8), cols (lane%4)*2
    #pragma unroll
    for (int mm = 0; mm < 2; mm++) {
        #pragma unroll
        for (int nf = 0; nf < 8; nf++) {
            const int c = colBase + nw * 64 + nf * 8 + (lane & 3) * 2;
            const int r0 = rowBase + mw * 32 + mm * 16 + (lane >> 2);
            if (MODE == 0) {
                const int three = c >> 9;
                const int head  = (c >> 5) & 15;
                const int d     = c & 31;
                __half* dst = (three == 0) ? g_qh : (three == 1) ? g_kh : g_vh;
                const float sc = (three == 0) ? C2F : 1.0f;   // fold scale*log2e into Q
                #pragma unroll
                for (int half = 0; half < 2; half++) {
                    const int r = r0 + half * 8;
                    const int b = r >> 10, n = r & 1023;
                    const size_t idx = (((size_t)(b * NHEAD + head) * NN) + n) * HD + d;
                    *(uint32_t*)(dst + idx) =
                        pack_h2(acc[mm][nf][half * 2] * sc, acc[mm][nf][half * 2 + 1] * sc);
                }
            } else {
                const float2 bv = *(const float2*)(bias + c);
                #pragma unroll
                for (int half = 0; half < 2; half++) {
                    const int r = r0 + half * 8;
                    float2 v = make_float2(acc[mm][nf][half * 2] + bv.x,
                                           acc[mm][nf][half * 2 + 1] + bv.y);
                    *(float2*)(out + (size_t)r * CD + c) = v;
                }
            }
        }
    }
}

// ---------------------------------------------------------------------------
// Tensor-core flash attention (fp16, single-term, MAX-FREE softmax).
// Q pre-scaled by scale*log2e, so p = ex2(s) directly; scores bounded
// (|s| <~ 10) -> unnormalized exp sums stay << fp32 range. No max tracking,
// no rescale, no shuffle chains in the mainloop.
// 256 thr / 8 warps; 128 q-rows per block, 16 per warp; 64-key tiles,
// 2-stage cp.async, SW64 swizzle. 2 CTAs/SM. grid = (NN/128, NHEAD, BB)
// ---------------------------------------------------------------------------
__global__ __launch_bounds__(256, 2) void attn_mma_kernel(float* __restrict__ y)
{
    constexpr int QBYTES = 128 * 64;          // 8192 (single Q matrix)
    constexpr int TMAT   = 64 * 64;           // 4096 per kv matrix
    constexpr int STAGE  = 2 * TMAT;          // 8192: kh, vh
    constexpr int NT     = NN / 64;           // 16 tiles

    extern __shared__ char dsm[];
    const uint32_t sQH = smem_u32(dsm);
    const uint32_t sKV = sQH + QBYTES;

    const int tid  = threadIdx.x;
    const int lane = tid & 31;
    const int wid  = tid >> 5;
    const int wr   = wid * 16;

    const int b = blockIdx.z;
    const int h = blockIdx.y;
    const int rowBase = blockIdx.x * 128;
    const size_t hb = ((size_t)(b * NHEAD + h)) * NN * HD;

    auto loadKV = [&](int t, int buf) {
        const uint32_t sb = sKV + buf * STAGE;
        const int row = tid >> 2, seg = tid & 3;
        const uint32_t so = sw64(row, seg);
        const size_t g = hb + (size_t)(t * 64 + row) * HD + seg * 8;
        cp_async16(sb + so,        g_kh + g);
        cp_async16(sb + TMAT + so, g_vh + g);
    };

    {   // Q load (single matrix: 128 rows x 4 segs = 512 cp / 256 thr) + KV tile 0
        {
            const int id  = tid * 2;
            const int row = id >> 2, seg = id & 3;
            const size_t g = hb + (size_t)(rowBase + row) * HD + seg * 8;
            cp_async16(sQH + sw64(row, seg),     g_qh + g);
            cp_async16(sQH + sw64(row, seg + 1), g_qh + g + 8);
        }
        loadKV(0, 0);
        CP_COMMIT();
    }

    float acc[4][4];
    #pragma unroll
    for (int a = 0; a < 4; a++)
        #pragma unroll
        for (int c = 0; c < 4; c++) acc[a][c] = 0.0f;
    float l0 = 0.0f, l1 = 0.0f;

    uint32_t qh[2][4];
    const int qRow = wr + (lane & 15);
    const int qSeg0 = lane >> 4;
    const int kRowL = lane & 7;               // + j*8
    const int kSeg = lane >> 3;
    const int vRowL = ((lane >> 3) & 1) * 8 + (lane & 7);   // + kk*16
    const int vSeg0 = lane >> 4;              // + 2*dp

    for (int t = 0; t < NT; t++) {
        if (t + 1 < NT) {
            loadKV(t + 1, (t + 1) & 1);
            CP_COMMIT();
            CP_WAIT1();
        } else {
            CP_WAIT0();
        }
        __syncthreads();

        if (t == 0) {
            #pragma unroll
            for (int kt = 0; kt < 2; kt++)
                LDSM_X4(qh[kt], sQH + sw64(qRow, qSeg0 + 2 * kt));
        }

        const uint32_t st = sKV + (t & 1) * STAGE;

        // ---- scores: S = Qh·Kh^T (Q pre-scaled) ----
        float s[8][4];
        #pragma unroll
        for (int j = 0; j < 8; j++) {
            uint32_t kf[4];
            LDSM_X4(kf, st + sw64(j * 8 + kRowL, kSeg));
            s[j][0] = s[j][1] = s[j][2] = s[j][3] = 0.0f;
            MMA16816(s[j], qh[0], kf[0], kf[1]);
            MMA16816(s[j], qh[1], kf[2], kf[3]);
        }

        // ---- max-free softmax: p = 2^s ----
        float ps0 = 0.0f, ps1 = 0.0f;
        #pragma unroll
        for (int j = 0; j < 8; j++) {
            s[j][0] = ex2(s[j][0]);
            s[j][1] = ex2(s[j][1]);
            s[j][2] = ex2(s[j][2]);
            s[j][3] = ex2(s[j][3]);
            ps0 += s[j][0] + s[j][1];
            ps1 += s[j][2] + s[j][3];
        }
        l0 += ps0;
        l1 += ps1;

        // ---- P·V: Ph·Vh ----
        #pragma unroll
        for (int kk = 0; kk < 4; kk++) {
            uint32_t ph[4];
            ph[0] = pack_h2(s[2 * kk][0],     s[2 * kk][1]);
            ph[1] = pack_h2(s[2 * kk][2],     s[2 * kk][3]);
            ph[2] = pack_h2(s[2 * kk + 1][0], s[2 * kk + 1][1]);
            ph[3] = pack_h2(s[2 * kk + 1][2], s[2 * kk + 1][3]);
            #pragma unroll
            for (int dp = 0; dp < 2; dp++) {
                uint32_t vh[4];
                LDSM_X4_T(vh, st + TMAT + sw64(kk * 16 + vRowL, vSeg0 + 2 * dp));
                MMA16816(acc[2 * dp],     ph, vh[0], vh[1]);
                MMA16816(acc[2 * dp + 1], ph, vh[2], vh[3]);
            }
        }
        __syncthreads();
    }

    l0 += __shfl_xor_sync(0xffffffffu, l0, 1);
    l0 += __shfl_xor_sync(0xffffffffu, l0, 2);
    l1 += __shfl_xor_sync(0xffffffffu, l1, 1);
    l1 += __shfl_xor_sync(0xffffffffu, l1, 2);
    const float inv0 = 1.0f / l0, inv1 = 1.0f / l1;

    const int r0 = rowBase + wr + (lane >> 2);
    const int cB = h * HD + (lane & 3) * 2;
    #pragma unroll
    for (int dn = 0; dn < 4; dn++) {
        *(float2*)(y + (size_t)(b * NN + r0) * CD + cB + dn * 8) =
            make_float2(acc[dn][0] * inv0, acc[dn][1] * inv0);
        *(float2*)(y + (size_t)(b * NN + r0 + 8) * CD + cB + dn * 8) =
            make_float2(acc[dn][2] * inv1, acc[dn][3] * inv1);
    }
}

// ---------------------------------------------------------------------------
// Smem-tiled LePE + to-fp16: yh = half( y_attn + dwconv5x5(x) + bias )
// CTA = 8x8 pixel tile x 64 channels; 12x12 halo of x in smem (36.9KB) +
// 64x25 weight chunk (6.4KB). grid = (W/8, H/8, B*8), block = 256.
// ---------------------------------------------------------------------------
__global__ __launch_bounds__(256) void lepe_tohalf_kernel(
    const float* __restrict__ x, const float* __restrict__ wl,
    const float* __restrict__ bl, const float* __restrict__ y,
    __half* __restrict__ yh)
{
    __shared__ float sx[12 * 12 * 64];   // halo tile
    __shared__ float sw[64 * 25];        // weights chunk

    const int tid = threadIdx.x;
    const int bx = blockIdx.x * 8;
    const int by = blockIdx.y * 8;
    const int b  = blockIdx.z >> 3;
    const int cc = (blockIdx.z & 7) * 64;

    // load x halo (zero-padded): 144 pixels x 16 float4
    for (int i = tid; i < 2304; i += 256) {
        const int p = i >> 4, f = i & 15;
        const int py = p / 12, px = p % 12;
        const int gy = by + py - 2, gx = bx + px - 2;
        float4 v = make_float4(0.f, 0.f, 0.f, 0.f);
        if (gy >= 0 && gy < HH && gx >= 0 && gx < WWI)
            v = *(const float4*)&x[(((size_t)(b * HH + gy) * WWI + gx)) * CD + cc + f * 4];
        *(float4*)&sx[(py * 12 + px) * 64 + f * 4] = v;
    }
    // load weights: wl[(cc..cc+63)][25] is contiguous from wl[cc*25]
    for (int i = tid; i < 1600; i += 256)
        sw[i] = wl[cc * 25 + i];
    __syncthreads();

    const int f  = tid & 15;             // channel float4 index
    const int pg = tid >> 4;             // pixel group 0..15 (4 pixels each)
    const int c0 = f * 4;
    const float4 bv = *(const float4*)&bl[cc + c0];

    float4 sum[4];
    #pragma unroll
    for (int pp = 0; pp < 4; pp++) sum[pp] = bv;

    #pragma unroll
    for (int ky = 0; ky < 5; ky++) {
        #pragma unroll
        for (int kx = 0; kx < 5; kx++) {
            const int wk = ky * 5 + kx;
            const float w0 = sw[(c0 + 0) * 25 + wk];
            const float w1 = sw[(c0 + 1) * 25 + wk];
            const float w2 = sw[(c0 + 2) * 25 + wk];
            const float w3 = sw[(c0 + 3) * 25 + wk];
            #pragma unroll
            for (int pp = 0; pp < 4; pp++) {
                const int p  = pg * 4 + pp;
                const int py = p >> 3, px = p & 7;
                const float4 xv = *(const float4*)&sx[((py + ky) * 12 + px + kx) * 64 + c0];
                sum[pp].x = fmaf(xv.x, w0, sum[pp].x);
                sum[pp].y = fmaf(xv.y, w1, sum[pp].y);
                sum[pp].z = fmaf(xv.z, w2, sum[pp].z);
                sum[pp].w = fmaf(xv.w, w3, sum[pp].w);
            }
        }
    }

    #pragma unroll
    for (int pp = 0; pp < 4; pp++) {
        const int p  = pg * 4 + pp;
        const int py = p >> 3, px = p & 7;
        const size_t idx = (((size_t)b * NN + (by + py) * WWI + (bx + px))) * CD + cc + c0;
        const float4 av = *(const float4*)&y[idx];
        uint32_t* H = (uint32_t*)(yh + idx);
        H[0] = pack_h2(sum[pp].x + av.x, sum[pp].y + av.y);
        H[1] = pack_h2(sum[pp].z + av.z, sum[pp].w + av.w);
    }
}

// ---------------------------------------------------------------------------
extern "C" void kernel_launch(void* const* d_in, const int* in_sizes, int n_in,
                              void* d_out, int out_size)
{
    const float* x      = (const float*)d_in[0];
    const float* w_qkv  = (const float*)d_in[1];
    const float* w_proj = (const float*)d_in[2];
    const float* b_proj = (const float*)d_in[3];
    const float* w_lepe = (const float*)d_in[4];
    const float* b_lepe = (const float*)d_in[5];
    float* out = (float*)d_out;

    float *yPtr;
    __half *xh, *yh, *wqh, *wph;
    cudaGetSymbolAddress((void**)&yPtr, g_y);
    cudaGetSymbolAddress((void**)&xh, g_xh);
    cudaGetSymbolAddress((void**)&yh, g_yh);
    cudaGetSymbolAddress((void**)&wqh, g_wqh);
    cudaGetSymbolAddress((void**)&wph, g_wph);

    constexpr int SMEM_GEMM = 2 * 2 * 128 * 64;                // 32768 B
    constexpr int SMEM_ATTN = 128 * 64 + 2 * 2 * 64 * 64;      // 24576 B
    cudaFuncSetAttribute(mma_gemm<0>, cudaFuncAttributeMaxDynamicSharedMemorySize, SMEM_GEMM);
    cudaFuncSetAttribute(mma_gemm<1>, cudaFuncAttributeMaxDynamicSharedMemorySize, SMEM_GEMM);
    cudaFuncSetAttribute(attn_mma_kernel, cudaFuncAttributeMaxDynamicSharedMemorySize, SMEM_ATTN);

    // 0) convert inputs/weights to fp16
    {
        int n4 = MTOT * CD / 4;
        tohalf_kernel<<<(n4 + 255) / 256, 256>>>(x, xh, n4);
        int w4 = 3 * CD * CD / 4;
        tohalf_kernel<<<(w4 + 255) / 256, 256>>>(w_qkv, wqh, w4);
        int p4 = CD * CD / 4;
        tohalf_kernel<<<(p4 + 255) / 256, 256>>>(w_proj, wph, p4);
    }
    // 1) QKV projection -> g_qh (x C2F), g_kh, g_vh   (M=8192, N=1536, K=512)
    {
        dim3 grid(3 * CD / 128, MTOT / 128);
        mma_gemm<0><<<grid, 256, SMEM_GEMM>>>(xh, wqh, nullptr, nullptr);
    }
    // 2) Attention -> g_y (fp32)
    {
        dim3 grid(NN / 128, NHEAD, BB);
        attn_mma_kernel<<<grid, 256, SMEM_ATTN>>>(yPtr);
    }
    // 3) Smem-tiled LePE + to-half -> g_yh
    {
        dim3 grid(WWI / 8, HH / 8, BB * 8);
        lepe_tohalf_kernel<<<grid, 256>>>(x, w_lepe, b_lepe, yPtr, yh);
    }
    // 4) Output projection -> d_out  (M=8192, N=512, K=512)
    {
        dim3 grid(CD / 128, MTOT / 128);
        mma_gemm<1><<<grid, 256, SMEM_GEMM>>>(yh, wph, b_proj, out);
    }
}